// round 2
// baseline (speedup 1.0000x reference)
#include <cuda_runtime.h>
#include <math.h>
#include <stdint.h>

#define EXER_N 10000
#define STU_N  20000
#define NTOT   30000
#define DD     128
#define HH     3
#define HD     384
#define CAP    96
#define BATCH  2048

// ---------------- scratch arena (device globals; no cudaMalloc allowed) ----
#define SZF(x) ((size_t)(x))
static constexpr size_t O_fE    = 0;                                   // 3*EXER_N*HD
static constexpr size_t O_elE   = O_fE    + SZF(3)*EXER_N*HD;
static constexpr size_t O_erD   = O_elE   + SZF(3)*EXER_N*3;
static constexpr size_t O_zE    = O_erD   + SZF(EXER_N)*3;
static constexpr size_t O_zlE   = O_zE    + SZF(3)*EXER_N*DD;
static constexpr size_t O_zrD   = O_zlE   + SZF(3)*EXER_N;
static constexpr size_t O_bz    = O_zrD   + SZF(EXER_N);
static constexpr size_t O_fS    = O_bz    + SZF(5)*DD;
static constexpr size_t O_elS   = O_fS    + SZF(STU_N)*HD;
static constexpr size_t O_erS   = O_elS   + SZF(STU_N)*3;
static constexpr size_t O_rst   = O_erS   + SZF(STU_N)*3;
static constexpr size_t O_zS    = O_rst   + SZF(STU_N)*HD;
static constexpr size_t O_zlS   = O_zS    + SZF(STU_N)*DD;
static constexpr size_t O_zrS   = O_zlS   + SZF(STU_N);
static constexpr size_t O_a     = O_zrS   + SZF(STU_N);
static constexpr size_t O_b     = O_a     + SZF(STU_N)*DD;
static constexpr size_t O_c     = O_b     + SZF(STU_N)*DD;
static constexpr size_t O_d     = O_c     + SZF(STU_N)*DD;
static constexpr size_t O_bp    = O_d     + SZF(STU_N)*DD;
static constexpr size_t O_stu1  = O_bp    + SZF(STU_N)*DD;
static constexpr size_t O_stu1p = O_stu1  + SZF(STU_N)*DD;
static constexpr size_t O_A2    = O_stu1p + SZF(STU_N)*DD;
static constexpr size_t O_B2    = O_A2    + SZF(STU_N)*DD;
static constexpr size_t O_stu2  = O_B2    + SZF(STU_N)*DD;
static constexpr size_t O_stu2p = O_stu2  + SZF(STU_N)*DD;
static constexpr size_t O_nb    = O_stu2p + SZF(STU_N)*DD;
static constexpr size_t O_nbp   = O_nb    + SZF(BATCH)*DD;
static constexpr size_t O_S     = O_nbp   + SZF(BATCH)*DD;
static constexpr size_t O_lossd = O_S     + DD;
static constexpr size_t F_TOT   = O_lossd + 4;

static constexpr size_t OI_adj  = 0;                      // 3*STU_N*CAP
static constexpr size_t OI_cnt  = SZF(3)*STU_N*CAP;
static constexpr size_t I_TOT   = OI_cnt + SZF(3)*STU_N;

__device__ __align__(256) float g_farena[F_TOT];
__device__ __align__(256) int   g_iarena[I_TOT];

// ---------------- SGEMM: C = A[MxK] @ B[KxN] (+C)(+bias)(+add) -------------
// row-major. N%128==0, K%16==0 required; M arbitrary.
// 128x128 block tile, BK=16, 256 threads, 8x8 per-thread micro-tile,
// double-buffered shared memory.
#define BM 128
#define BN 128
#define BK 16

__global__ __launch_bounds__(256, 2)
void sgemm(const float* __restrict__ A, const float* __restrict__ B,
           float* __restrict__ C, int M, int N, int K,
           const float* __restrict__ bias,
           const float* __restrict__ addm,
           int accumulate)
{
    __shared__ float As[2][BK][BM];
    __shared__ float Bs[2][BK][BN];

    const int tid = threadIdx.x;                 // 256 threads
    const int bm  = blockIdx.y * BM;
    const int bn  = blockIdx.x * BN;
    const int ty  = tid >> 4;                    // 0..15 (row group)
    const int tx  = tid & 15;                    // 0..15 (col group)

    // Load index mapping (per 128x16 A-tile: 512 float4; per 16x128 B-tile: 512 float4)
    // each thread handles 2 float4 of A and 2 of B per tile.
    const int qa0 = tid, qa1 = tid + 256;
    const int ar0 = qa0 >> 2, ac0 = (qa0 & 3) * 4;
    const int ar1 = qa1 >> 2, ac1 = (qa1 & 3) * 4;
    const int br0 = qa0 >> 5, bc0 = (qa0 & 31) * 4;
    const int br1 = qa1 >> 5, bc1 = (qa1 & 31) * 4;

    float acc[8][8];
#pragma unroll
    for (int i = 0; i < 8; i++)
#pragma unroll
        for (int j = 0; j < 8; j++) acc[i][j] = 0.f;

    const int nt = K / BK;

    float4 a_rg0, a_rg1, b_rg0, b_rg1;

    // prologue: load tile 0 into regs
    {
        const int k0 = 0;
        a_rg0 = (bm + ar0 < M) ? *(const float4*)(A + (size_t)(bm + ar0) * K + k0 + ac0)
                               : make_float4(0.f, 0.f, 0.f, 0.f);
        a_rg1 = (bm + ar1 < M) ? *(const float4*)(A + (size_t)(bm + ar1) * K + k0 + ac1)
                               : make_float4(0.f, 0.f, 0.f, 0.f);
        b_rg0 = *(const float4*)(B + (size_t)(k0 + br0) * N + bn + bc0);
        b_rg1 = *(const float4*)(B + (size_t)(k0 + br1) * N + bn + bc1);
    }
    // store tile 0 into buf 0
    {
        As[0][ac0 + 0][ar0] = a_rg0.x; As[0][ac0 + 1][ar0] = a_rg0.y;
        As[0][ac0 + 2][ar0] = a_rg0.z; As[0][ac0 + 3][ar0] = a_rg0.w;
        As[0][ac1 + 0][ar1] = a_rg1.x; As[0][ac1 + 1][ar1] = a_rg1.y;
        As[0][ac1 + 2][ar1] = a_rg1.z; As[0][ac1 + 3][ar1] = a_rg1.w;
        *(float4*)(&Bs[0][br0][bc0]) = b_rg0;
        *(float4*)(&Bs[0][br1][bc1]) = b_rg1;
    }
    __syncthreads();

    for (int kt = 0; kt < nt; kt++) {
        const int cur = kt & 1;
        const int nxt = cur ^ 1;
        const bool more = (kt + 1 < nt);
        if (more) {
            const int k0 = (kt + 1) * BK;
            a_rg0 = (bm + ar0 < M) ? *(const float4*)(A + (size_t)(bm + ar0) * K + k0 + ac0)
                                   : make_float4(0.f, 0.f, 0.f, 0.f);
            a_rg1 = (bm + ar1 < M) ? *(const float4*)(A + (size_t)(bm + ar1) * K + k0 + ac1)
                                   : make_float4(0.f, 0.f, 0.f, 0.f);
            b_rg0 = *(const float4*)(B + (size_t)(k0 + br0) * N + bn + bc0);
            b_rg1 = *(const float4*)(B + (size_t)(k0 + br1) * N + bn + bc1);
        }
#pragma unroll
        for (int k = 0; k < BK; k++) {
            float4 a0 = *(const float4*)(&As[cur][k][ty * 8]);
            float4 a1 = *(const float4*)(&As[cur][k][ty * 8 + 4]);
            float4 b0 = *(const float4*)(&Bs[cur][k][tx * 8]);
            float4 b1 = *(const float4*)(&Bs[cur][k][tx * 8 + 4]);
            float am[8] = {a0.x, a0.y, a0.z, a0.w, a1.x, a1.y, a1.z, a1.w};
            float bv[8] = {b0.x, b0.y, b0.z, b0.w, b1.x, b1.y, b1.z, b1.w};
#pragma unroll
            for (int i = 0; i < 8; i++)
#pragma unroll
                for (int j = 0; j < 8; j++) acc[i][j] += am[i] * bv[j];
        }
        if (more) {
            As[nxt][ac0 + 0][ar0] = a_rg0.x; As[nxt][ac0 + 1][ar0] = a_rg0.y;
            As[nxt][ac0 + 2][ar0] = a_rg0.z; As[nxt][ac0 + 3][ar0] = a_rg0.w;
            As[nxt][ac1 + 0][ar1] = a_rg1.x; As[nxt][ac1 + 1][ar1] = a_rg1.y;
            As[nxt][ac1 + 2][ar1] = a_rg1.z; As[nxt][ac1 + 3][ar1] = a_rg1.w;
            *(float4*)(&Bs[nxt][br0][bc0]) = b_rg0;
            *(float4*)(&Bs[nxt][br1][bc1]) = b_rg1;
        }
        __syncthreads();
    }

    // epilogue
#pragma unroll
    for (int i = 0; i < 8; i++) {
        const int m = bm + ty * 8 + i;
        if (m >= M) continue;
#pragma unroll
        for (int j = 0; j < 8; j += 4) {
            const int n = bn + tx * 8 + j;
            float4 v = make_float4(acc[i][j], acc[i][j + 1], acc[i][j + 2], acc[i][j + 3]);
            if (accumulate) {
                float4 o = *(const float4*)(C + (size_t)m * N + n);
                v.x += o.x; v.y += o.y; v.z += o.z; v.w += o.w;
            }
            if (bias) {
                v.x += bias[n]; v.y += bias[n + 1]; v.z += bias[n + 2]; v.w += bias[n + 3];
            }
            if (addm) {
                float4 o = *(const float4*)(addm + (size_t)m * N + n);
                v.x += o.x; v.y += o.y; v.z += o.z; v.w += o.w;
            }
            *(float4*)(C + (size_t)m * N + n) = v;
        }
    }
}

// ---------------- small utility kernels ------------------------------------
__global__ void zero_int(int* p, int n) {
    int i = blockIdx.x * blockDim.x + threadIdx.x;
    if (i < n) p[i] = 0;
}

__global__ void copy_f(const float* __restrict__ s, float* __restrict__ d, int n) {
    int i = blockIdx.x * blockDim.x + threadIdx.x;
    if (i < n) d[i] = s[i];
}

// adjacency buckets by (dst - EXER_N); only stu dst kept
__global__ void build_adj(const int* __restrict__ src, const int* __restrict__ dst,
                          int ecnt, int* __restrict__ adj, int* __restrict__ cnt) {
    int i = blockIdx.x * blockDim.x + threadIdx.x;
    if (i >= ecnt) return;
    int d = dst[i];
    if (d < EXER_N) return;
    int dl = d - EXER_N;
    int slot = atomicAdd(&cnt[dl], 1);
    if (slot < CAP) adj[(size_t)dl * CAP + slot] = src[i];
}

// bz[p] = gat_b[p] @ fc_W[p] + fc_b[p]   (per-layer effective bias, 128-vec)
__global__ void bz_kernel(const float* __restrict__ gb, const float* __restrict__ fcW,
                          const float* __restrict__ fcb, float* __restrict__ bz) {
    int p = blockIdx.x, n = threadIdx.x;   // 5 blocks x 128
    const float* g = gb + (size_t)p * HD;
    const float* W = fcW + (size_t)p * HD * DD;
    float s = fcb[(size_t)p * DD + n];
    for (int k = 0; k < HD; k++) s += g[k] * W[(size_t)k * DD + n];
    bz[(size_t)p * DD + n] = s;
}

// el[n,h]=sum_d f[n,h,d]*al[h,d], er likewise. 1 block/node, 128 threads.
__global__ void el_er_kernel(const float* __restrict__ f, const float* __restrict__ al,
                             const float* __restrict__ ar,
                             float* __restrict__ el, float* __restrict__ er) {
    int n = blockIdx.x, t = threadIdx.x;
    const float* fr = f + (size_t)n * HD;
    float pel[3], per[3];
#pragma unroll
    for (int h = 0; h < 3; h++) {
        float v = fr[h * DD + t];
        pel[h] = v * al[h * DD + t];
        per[h] = v * ar[h * DD + t];
    }
#pragma unroll
    for (int off = 16; off; off >>= 1) {
#pragma unroll
        for (int h = 0; h < 3; h++) {
            pel[h] += __shfl_xor_sync(0xffffffffu, pel[h], off);
            per[h] += __shfl_xor_sync(0xffffffffu, per[h], off);
        }
    }
    __shared__ float red[4][6];
    int w = t >> 5;
    if ((t & 31) == 0) {
#pragma unroll
        for (int h = 0; h < 3; h++) { red[w][h] = pel[h]; red[w][3 + h] = per[h]; }
    }
    __syncthreads();
    if (t < 6) {
        float v = red[0][t] + red[1][t] + red[2][t] + red[3][t];
        if (t < 3) el[(size_t)n * 3 + t] = v;
        else       er[(size_t)n * 3 + (t - 3)] = v;
    }
}

// zl[n]=z[n]·aW[:128], zr[n]=z[n]·aW[128:]
__global__ void zlzr_kernel(const float* __restrict__ z, const float* __restrict__ aW,
                            float* __restrict__ zl, float* __restrict__ zr) {
    int n = blockIdx.x, t = threadIdx.x;
    float v = z[(size_t)n * DD + t];
    float a = v * aW[t];
    float b = v * aW[DD + t];
#pragma unroll
    for (int off = 16; off; off >>= 1) {
        a += __shfl_xor_sync(0xffffffffu, a, off);
        b += __shfl_xor_sync(0xffffffffu, b, off);
    }
    __shared__ float red[4][2];
    int w = t >> 5;
    if ((t & 31) == 0) { red[w][0] = a; red[w][1] = b; }
    __syncthreads();
    if (t < 2) {
        float v2 = red[0][t] + red[1][t] + red[2][t] + red[3][t];
        if (t == 0) zl[n] = v2; else zr[n] = v2;
    }
}

// attention stage 1: softmax over incoming edges (3 heads) + weighted f-sum
__global__ void attn1_kernel(const int* __restrict__ adj, const int* __restrict__ cnt,
                             const float* __restrict__ elE, const float* __restrict__ elS,
                             const float* __restrict__ erS,
                             const float* __restrict__ fE, const float* __restrict__ fS,
                             float* __restrict__ rst) {
    int dl = blockIdx.x, t = threadIdx.x;
    int deg = cnt[dl]; if (deg > CAP) deg = CAP;
    __shared__ int   ssrc[CAP];
    __shared__ float se[CAP * 3];
    __shared__ float sm[3], ssum[3];
    float er0 = erS[(size_t)dl * 3 + 0];
    float er1 = erS[(size_t)dl * 3 + 1];
    float er2 = erS[(size_t)dl * 3 + 2];
    if (t < deg) {
        int s = adj[(size_t)dl * CAP + t];
        ssrc[t] = s;
        const float* el = (s < EXER_N) ? (elE + (size_t)s * 3) : (elS + (size_t)(s - EXER_N) * 3);
        float e0 = el[0] + er0, e1 = el[1] + er1, e2 = el[2] + er2;
        se[t * 3 + 0] = e0 > 0.f ? e0 : 0.2f * e0;
        se[t * 3 + 1] = e1 > 0.f ? e1 : 0.2f * e1;
        se[t * 3 + 2] = e2 > 0.f ? e2 : 0.2f * e2;
    }
    __syncthreads();
    int w = t >> 5, lane = t & 31;
    if (w < 3) {
        float m = -3.0e38f;
        for (int j = lane; j < deg; j += 32) m = fmaxf(m, se[j * 3 + w]);
#pragma unroll
        for (int off = 16; off; off >>= 1) m = fmaxf(m, __shfl_xor_sync(0xffffffffu, m, off));
        float s = 0.f;
        for (int j = lane; j < deg; j += 32) s += expf(se[j * 3 + w] - m);
#pragma unroll
        for (int off = 16; off; off >>= 1) s += __shfl_xor_sync(0xffffffffu, s, off);
        if (lane == 0) { sm[w] = m; ssum[w] = s; }
    }
    __syncthreads();
    if (t < deg) {
#pragma unroll
        for (int h = 0; h < 3; h++)
            se[t * 3 + h] = expf(se[t * 3 + h] - sm[h]) / ssum[h];
    }
    __syncthreads();
    float a0 = 0.f, a1 = 0.f, a2 = 0.f;
    for (int j = 0; j < deg; j++) {
        int s = ssrc[j];
        const float* fr = (s < EXER_N) ? (fE + (size_t)s * HD) : (fS + (size_t)(s - EXER_N) * HD);
        float w0 = se[j * 3 + 0], w1 = se[j * 3 + 1], w2 = se[j * 3 + 2];
        a0 += w0 * fr[t];
        a1 += w1 * fr[DD + t];
        a2 += w2 * fr[2 * DD + t];
    }
    size_t o = (size_t)dl * HD;
    rst[o + t] = a0; rst[o + DD + t] = a1; rst[o + 2 * DD + t] = a2;
}

// attention stage 2: 1-head softmax + weighted z-sum
__global__ void attn2_kernel(const int* __restrict__ adj, const int* __restrict__ cnt,
                             const float* __restrict__ zlE, const float* __restrict__ zlS,
                             const float* __restrict__ zrS,
                             const float* __restrict__ zE, const float* __restrict__ zS,
                             float* __restrict__ out) {
    int dl = blockIdx.x, t = threadIdx.x;
    int deg = cnt[dl]; if (deg > CAP) deg = CAP;
    __shared__ int   ssrc[CAP];
    __shared__ float se[CAP];
    __shared__ float smx, ssm;
    float zr = zrS[dl];
    if (t < deg) {
        int s = adj[(size_t)dl * CAP + t];
        ssrc[t] = s;
        float zl = (s < EXER_N) ? zlE[s] : zlS[s - EXER_N];
        se[t] = zl + zr;     // NOTE: no leaky_relu on second attention
    }
    __syncthreads();
    if (t < 32) {
        float m = -3.0e38f;
        for (int j = t; j < deg; j += 32) m = fmaxf(m, se[j]);
#pragma unroll
        for (int off = 16; off; off >>= 1) m = fmaxf(m, __shfl_xor_sync(0xffffffffu, m, off));
        float s = 0.f;
        for (int j = t; j < deg; j += 32) s += expf(se[j] - m);
#pragma unroll
        for (int off = 16; off; off >>= 1) s += __shfl_xor_sync(0xffffffffu, s, off);
        if (t == 0) { smx = m; ssm = s; }
    }
    __syncthreads();
    if (t < deg) se[t] = expf(se[t] - smx) / ssm;
    __syncthreads();
    float acc = 0.f;
    for (int j = 0; j < deg; j++) {
        int s = ssrc[j];
        const float* zrow = (s < EXER_N) ? (zE + (size_t)s * DD) : (zS + (size_t)(s - EXER_N) * DD);
        acc += se[j] * zrow[t];
    }
    out[(size_t)dl * DD + t] = acc;
}

// SSL pieces --------------------------------------------------------------
__global__ void norm_rows(const float* __restrict__ emb, const int* __restrict__ ids,
                          float* __restrict__ out) {
    int i = blockIdx.x, t = threadIdx.x;    // BATCH blocks x 128
    int r = ids[i];
    float v = emb[(size_t)r * DD + t];
    float sq = v * v;
#pragma unroll
    for (int off = 16; off; off >>= 1) sq += __shfl_xor_sync(0xffffffffu, sq, off);
    __shared__ float w4[4];
    if ((t & 31) == 0) w4[t >> 5] = sq;
    __syncthreads();
    float tot = w4[0] + w4[1] + w4[2] + w4[3];
    float nrm = sqrtf(tot);
    out[(size_t)i * DD + t] = v / fmaxf(nrm, 1e-12f);
}

__global__ void colsum(const float* __restrict__ nbp, float* __restrict__ S) {
    int t = threadIdx.x;   // 1 block x 128
    float s = 0.f;
    for (int i = 0; i < BATCH; i++) s += nbp[(size_t)i * DD + t];
    S[t] = s;
}

__global__ void loss_kernel(const float* __restrict__ nb, const float* __restrict__ nbp,
                            const float* __restrict__ S, float* __restrict__ out) {
    int t = threadIdx.x;   // 1 block x 256
    float lsum = 0.f;
    for (int i = t; i < BATCH; i += 256) {
        const float* x = nb  + (size_t)i * DD;
        const float* y = nbp + (size_t)i * DD;
        float dg = 0.f, rs = 0.f;
        for (int d = 0; d < DD; d++) {
            float xv = x[d];
            dg += xv * y[d];
            rs += xv * S[d];
        }
        float diag   = dg * 5.0f;            // /0.2
        float rowsum = rs * 5.0f;
        float divided = expf(diag) / (rowsum + 1e-8f);
        float v = fmaxf(divided, 1e-8f);
        lsum += -logf(v);
    }
    __shared__ float red[256];
    red[t] = lsum;
    __syncthreads();
    for (int s = 128; s; s >>= 1) { if (t < s) red[t] += red[t + s]; __syncthreads(); }
    if (t == 0) out[0] = red[0];
}

// ---------------- host orchestration ---------------------------------------
extern "C" void kernel_launch(void* const* d_in, const int* in_sizes, int n_in,
                              void* d_out_, int out_size)
{
    const float* stu_table  = (const float*)d_in[0];
    const float* exer_table = (const float*)d_in[1];
    const float* gat_W  = (const float*)d_in[2];
    const float* attn_l = (const float*)d_in[3];
    const float* attn_r = (const float*)d_in[4];
    const float* gat_b  = (const float*)d_in[5];
    const float* fc_W   = (const float*)d_in[6];
    const float* fc_b   = (const float*)d_in[7];
    const float* aW     = (const float*)d_in[8];
    const float* f1W    = (const float*)d_in[9];
    const float* f1b    = (const float*)d_in[10];
    const float* f2W    = (const float*)d_in[11];
    const float* f2b    = (const float*)d_in[12];
    const int* e_src[3] = {(const int*)d_in[13], (const int*)d_in[15], (const int*)d_in[21]};
    const int* e_dst[3] = {(const int*)d_in[14], (const int*)d_in[16], (const int*)d_in[22]};
    int e_n[3] = {in_sizes[13], in_sizes[15], in_sizes[21]};
    const int* stu_id = (const int*)d_in[23];
    float* d_out = (float*)d_out_;
    (void)n_in;

    float* FA = nullptr; int* IA = nullptr;
    cudaGetSymbolAddress((void**)&FA, g_farena);
    cudaGetSymbolAddress((void**)&IA, g_iarena);

    float* fE    = FA + O_fE;
    float* elE   = FA + O_elE;
    float* erD   = FA + O_erD;
    float* zE    = FA + O_zE;
    float* zlE   = FA + O_zlE;
    float* zrD   = FA + O_zrD;
    float* bz    = FA + O_bz;
    float* fS    = FA + O_fS;
    float* elS   = FA + O_elS;
    float* erS   = FA + O_erS;
    float* rst   = FA + O_rst;
    float* zS    = FA + O_zS;
    float* zlS   = FA + O_zlS;
    float* zrS   = FA + O_zrS;
    float* abuf  = FA + O_a;
    float* bbuf  = FA + O_b;
    float* cbuf  = FA + O_c;
    float* dbuf  = FA + O_d;
    float* bpbuf = FA + O_bp;
    float* stu1  = FA + O_stu1;
    float* stu1p = FA + O_stu1p;
    float* A2    = FA + O_A2;
    float* B2    = FA + O_B2;
    float* stu2  = FA + O_stu2;
    float* stu2p = FA + O_stu2p;
    float* nb    = FA + O_nb;
    float* nbp   = FA + O_nbp;
    float* Sv    = FA + O_S;
    float* lossD = FA + O_lossd;

    const int pidx[3] = {0, 1, 4};   // param slots for edge-bearing layers

    // effective biases (per layer): bz = gat_b @ fc_W + fc_b
    bz_kernel<<<5, 128>>>(gat_b, fc_W, fc_b, bz);

    const int gM_E = (EXER_N + BM - 1) / BM;
    const int gM_S = (STU_N + BM - 1) / BM;

    // ---- per-slot: adjacency + exer-side invariants ----
    for (int s = 0; s < 3; s++) {
        int p = pidx[s];
        int* adj = IA + OI_adj + (size_t)s * STU_N * CAP;
        int* cnt = IA + OI_cnt + (size_t)s * STU_N;
        zero_int<<<(STU_N + 255) / 256, 256>>>(cnt, STU_N);
        build_adj<<<(e_n[s] + 255) / 256, 256>>>(e_src[s], e_dst[s], e_n[s], adj, cnt);

        float* fEs  = fE  + (size_t)s * EXER_N * HD;
        float* zEs  = zE  + (size_t)s * EXER_N * DD;
        float* elEs = elE + (size_t)s * EXER_N * 3;
        float* zlEs = zlE + (size_t)s * EXER_N;

        sgemm<<<dim3(HD / BN, gM_E), 256>>>(exer_table, gat_W + (size_t)p * DD * HD,
                                            fEs, EXER_N, HD, DD, nullptr, nullptr, 0);
        el_er_kernel<<<EXER_N, 128>>>(fEs, attn_l + (size_t)p * HD, attn_r + (size_t)p * HD,
                                      elEs, erD);
        sgemm<<<dim3(DD / BN, gM_E), 256>>>(fEs, fc_W + (size_t)p * HD * DD,
                                            zEs, EXER_N, DD, HD, bz + (size_t)p * DD, nullptr, 0);
        zlzr_kernel<<<EXER_N, 128>>>(zEs, aW + (size_t)p * 2 * DD, zlEs, zrD);
    }

    // ---- layers 2,3 at stu rows: pure per-node transform (self-loop only) ----
    for (int p = 2; p <= 3; p++) {
        float* outp = (p == 2) ? cbuf : dbuf;
        sgemm<<<dim3(HD / BN, gM_S), 256>>>(stu_table, gat_W + (size_t)p * DD * HD,
                                            fS, STU_N, HD, DD, nullptr, nullptr, 0);
        sgemm<<<dim3(DD / BN, gM_S), 256>>>(fS, fc_W + (size_t)p * HD * DD,
                                            outp, STU_N, DD, HD, bz + (size_t)p * DD, nullptr, 0);
    }

    // ---- one GAT invocation (stu rows only) ----
    auto run_gat = [&](int s, const float* xS, float* outb) {
        int p = pidx[s];
        const int* adj = IA + OI_adj + (size_t)s * STU_N * CAP;
        const int* cnt = IA + OI_cnt + (size_t)s * STU_N;
        const float* fEs  = fE  + (size_t)s * EXER_N * HD;
        const float* zEs  = zE  + (size_t)s * EXER_N * DD;
        const float* elEs = elE + (size_t)s * EXER_N * 3;
        const float* zlEs = zlE + (size_t)s * EXER_N;

        sgemm<<<dim3(HD / BN, gM_S), 256>>>(xS, gat_W + (size_t)p * DD * HD,
                                            fS, STU_N, HD, DD, nullptr, nullptr, 0);
        el_er_kernel<<<STU_N, 128>>>(fS, attn_l + (size_t)p * HD, attn_r + (size_t)p * HD,
                                     elS, erS);
        attn1_kernel<<<STU_N, 128>>>(adj, cnt, elEs, elS, erS, fEs, fS, rst);
        sgemm<<<dim3(DD / BN, gM_S), 256>>>(rst, fc_W + (size_t)p * HD * DD,
                                            zS, STU_N, DD, HD, bz + (size_t)p * DD, nullptr, 0);
        zlzr_kernel<<<STU_N, 128>>>(zS, aW + (size_t)p * 2 * DD, zlS, zrS);
        attn2_kernel<<<STU_N, 128>>>(adj, cnt, zlEs, zlS, zrS, zEs, zS, outb);
    };

    // first round on base tables
    run_gat(0, stu_table, abuf);
    run_gat(1, stu_table, bbuf);
    run_gat(2, stu_table, bpbuf);

    // fusion1: stu1 = stu_table + [a|b|c|d]@f1W + f1b  (and stu1p with bp)
    auto fuse1 = [&](const float* bsel, float* dst) {
        sgemm<<<dim3(DD / BN, gM_S), 256>>>(abuf, f1W,              dst, STU_N, DD, DD, nullptr, nullptr, 0);
        sgemm<<<dim3(DD / BN, gM_S), 256>>>(bsel, f1W + 128 * 128,  dst, STU_N, DD, DD, nullptr, nullptr, 1);
        sgemm<<<dim3(DD / BN, gM_S), 256>>>(cbuf, f1W + 256 * 128,  dst, STU_N, DD, DD, nullptr, nullptr, 1);
        sgemm<<<dim3(DD / BN, gM_S), 256>>>(dbuf, f1W + 384 * 128,  dst, STU_N, DD, DD, f1b, stu_table, 1);
    };
    fuse1(bbuf, stu1);
    fuse1(bpbuf, stu1p);

    // expr2(stu1) -> stu2
    run_gat(0, stu1, A2);
    run_gat(1, stu1, B2);
    sgemm<<<dim3(DD / BN, gM_S), 256>>>(A2, f2W,             stu2, STU_N, DD, DD, nullptr, nullptr, 0);
    sgemm<<<dim3(DD / BN, gM_S), 256>>>(B2, f2W + 128 * 128, stu2, STU_N, DD, DD, f2b, stu1, 1);

    // expr2(stu1p) -> stu2p
    run_gat(0, stu1p, A2);
    run_gat(1, stu1p, B2);
    sgemm<<<dim3(DD / BN, gM_S), 256>>>(A2, f2W,             stu2p, STU_N, DD, DD, nullptr, nullptr, 0);
    sgemm<<<dim3(DD / BN, gM_S), 256>>>(B2, f2W + 128 * 128, stu2p, STU_N, DD, DD, f2b, stu1p, 1);

    // ---- outputs ----
    const int NOUT = STU_N * DD;
    if (out_size >= NOUT)
        copy_f<<<(NOUT + 255) / 256, 256>>>(stu2, d_out, NOUT);

    float* lossdst = lossD;
    if (out_size == 1) lossdst = d_out;
    else if (out_size > NOUT) lossdst = d_out + (out_size - 1);

    norm_rows<<<BATCH, 128>>>(stu2,  stu_id, nb);
    norm_rows<<<BATCH, 128>>>(stu2p, stu_id, nbp);
    colsum<<<1, 128>>>(nbp, Sv);
    loss_kernel<<<1, 256>>>(nb, nbp, Sv, lossdst);
}

// round 4
// speedup vs baseline: 1.1058x; 1.1058x over previous
#include <cuda_runtime.h>
#include <math.h>
#include <stdint.h>

#define EXER_N 10000
#define STU_N  20000
#define DD     128
#define HH     3
#define HD     384
#define CAP    96
#define BATCH  2048

#define SZF(x) ((size_t)(x))

// ---------------- scratch arena ---------------------------------------------
static constexpr size_t O_fE    = 0;                                    // 3*EXER_N*HD
static constexpr size_t O_elE   = O_fE    + SZF(3)*EXER_N*HD;
static constexpr size_t O_erD   = O_elE   + SZF(3)*EXER_N*3;            // dump
static constexpr size_t O_zE    = O_erD   + SZF(EXER_N)*3;
static constexpr size_t O_zlE   = O_zE    + SZF(3)*EXER_N*DD;
static constexpr size_t O_zrD   = O_zlE   + SZF(3)*EXER_N;              // dump
static constexpr size_t O_bz    = O_zrD   + SZF(EXER_N);
static constexpr size_t O_ABCD  = O_bz    + SZF(5)*DD;                  // 20000x512
static constexpr size_t O_ABPCD = O_ABCD  + SZF(STU_N)*4*DD;            // 20000x512
static constexpr size_t O_stu1  = O_ABPCD + SZF(STU_N)*4*DD;
static constexpr size_t O_stu1p = O_stu1  + SZF(STU_N)*DD;
static constexpr size_t O_XYX   = O_stu1p + SZF(STU_N)*DD;              // 20000x256
static constexpr size_t O_XYP   = O_XYX   + SZF(STU_N)*2*DD;            // 20000x256
static constexpr size_t O_stu2  = O_XYP   + SZF(STU_N)*2*DD;
static constexpr size_t O_stu2p = O_stu2  + SZF(STU_N)*DD;
static constexpr size_t O_nb    = O_stu2p + SZF(STU_N)*DD;
static constexpr size_t O_nbp   = O_nb    + SZF(BATCH)*DD;
static constexpr size_t O_S     = O_nbp   + SZF(BATCH)*DD;
static constexpr size_t O_lossd = O_S     + DD;
static constexpr size_t O_SCR   = O_lossd + 16;
// per-instance scratch set (x4)
static constexpr size_t SC_fS   = 0;                                    // STU_N*HD
static constexpr size_t SC_elS  = SC_fS  + SZF(STU_N)*HD;
static constexpr size_t SC_erS  = SC_elS + SZF(STU_N)*3;
static constexpr size_t SC_rst  = SC_erS + SZF(STU_N)*3;
static constexpr size_t SC_zS   = SC_rst + SZF(STU_N)*HD;
static constexpr size_t SC_zlS  = SC_zS  + SZF(STU_N)*DD;
static constexpr size_t SC_zrS  = SC_zlS + SZF(STU_N);
static constexpr size_t SC_TOT  = SC_zrS + SZF(STU_N);
static constexpr size_t F_TOT   = O_SCR + 4*SC_TOT;

static constexpr size_t OI_adj  = 0;                                    // 3*STU_N*CAP
static constexpr size_t OI_cnt  = SZF(3)*STU_N*CAP;
static constexpr size_t I_TOT   = OI_cnt + SZF(3)*STU_N;

__device__ __align__(256) float g_farena[F_TOT];
__device__ __align__(256) int   g_iarena[I_TOT];

// ---------------- batched pointer structs ------------------------------------
struct GB {                       // batched GEMM args (<=4 instances)
    const float* A[4];
    const float* B[4];
    float*       C[4];
    float*       C2[4];
    const float* bias[4];
    const float* addm[4];
};
struct EEB {                      // batched el_er
    const float* f[4];
    const float* al[4];
    const float* ar[4];
    float*       el[4];
    float*       er[4];
};
struct ZZB {                      // batched zlzr
    const float* z[4];
    const float* aW[4];
    float*       zl[4];
    float*       zr[4];
};
struct A1B {                      // batched attn1
    const int*   adj[4];
    const int*   cnt[4];
    const float* elE[4];
    const float* elS[4];
    const float* erS[4];
    const float* fE[4];
    const float* fS[4];
    float*       rst[4];
};
struct A2B {                      // batched attn2
    const int*   adj[4];
    const int*   cnt[4];
    const float* zlE[4];
    const float* zlS[4];
    const float* zrS[4];
    const float* zE[4];
    const float* zS[4];
    float*       out[4];
    float*       out2[4];
};
struct ADJB {                     // batched adjacency build
    const int* src[3];
    const int* dst[3];
    int        ecnt[3];
    int*       adj[3];
    int*       cnt[3];
};
struct NRB {                      // batched norm_rows
    const float* emb[2];
    float*       out[2];
};

// ---------------- batched SGEMM: C = A[MxK](lda) @ B[KxN] (+bias)(+addm) -----
// 64x64 tile, BK=16, 256 threads, 4x4 micro-tile. N%64==0, K%16==0.
__global__ __launch_bounds__(256)
void sgemm_b(GB g, int lda, int ldc, int ldadd, int M, int N, int K)
{
    const int z = blockIdx.z;
    const float* __restrict__ A    = g.A[z];
    const float* __restrict__ B    = g.B[z];
    float*       __restrict__ C    = g.C[z];
    float*                    C2   = g.C2[z];
    const float*              bias = g.bias[z];
    const float*              addm = g.addm[z];

    __shared__ float As[16][64];
    __shared__ float Bs[16][64];
    const int tid = threadIdx.x;
    const int bm  = blockIdx.y * 64;
    const int bn  = blockIdx.x * 64;
    const int ty  = tid >> 4;
    const int tx  = tid & 15;
    const int la_m = tid >> 2;
    const int la_k = (tid & 3) * 4;
    const int lb_k = tid >> 4;
    const int lb_n = (tid & 15) * 4;

    float acc[4][4];
#pragma unroll
    for (int i = 0; i < 4; i++)
#pragma unroll
        for (int j = 0; j < 4; j++) acc[i][j] = 0.f;

    for (int k0 = 0; k0 < K; k0 += 16) {
        float4 av;
        if (bm + la_m < M) av = *(const float4*)(A + (size_t)(bm + la_m) * lda + k0 + la_k);
        else av = make_float4(0.f, 0.f, 0.f, 0.f);
        As[la_k + 0][la_m] = av.x;
        As[la_k + 1][la_m] = av.y;
        As[la_k + 2][la_m] = av.z;
        As[la_k + 3][la_m] = av.w;
        float4 bv = *(const float4*)(B + (size_t)(k0 + lb_k) * N + bn + lb_n);
        *(float4*)(&Bs[lb_k][lb_n]) = bv;
        __syncthreads();
#pragma unroll
        for (int k = 0; k < 16; k++) {
            float am[4], bnv[4];
#pragma unroll
            for (int i = 0; i < 4; i++) am[i]  = As[k][ty * 4 + i];
#pragma unroll
            for (int j = 0; j < 4; j++) bnv[j] = Bs[k][tx * 4 + j];
#pragma unroll
            for (int i = 0; i < 4; i++)
#pragma unroll
                for (int j = 0; j < 4; j++) acc[i][j] += am[i] * bnv[j];
        }
        __syncthreads();
    }
#pragma unroll
    for (int i = 0; i < 4; i++) {
        int m = bm + ty * 4 + i;
        if (m >= M) continue;
#pragma unroll
        for (int j = 0; j < 4; j++) {
            int n = bn + tx * 4 + j;
            float v = acc[i][j];
            if (bias) v += bias[n];
            if (addm) v += addm[(size_t)m * ldadd + n];
            C[(size_t)m * ldc + n] = v;
            if (C2) C2[(size_t)m * ldc + n] = v;
        }
    }
}

// ---------------- small batched kernels ---------------------------------------
__global__ void zero_int(int* p, int n) {
    int i = blockIdx.x * blockDim.x + threadIdx.x;
    if (i < n) p[i] = 0;
}
__global__ void copy_f(const float* __restrict__ s, float* __restrict__ d, int n) {
    int i = blockIdx.x * blockDim.x + threadIdx.x;
    if (i < n) d[i] = s[i];
}
__global__ void build_adj_b(ADJB g) {
    int z = blockIdx.y;
    int i = blockIdx.x * blockDim.x + threadIdx.x;
    if (i >= g.ecnt[z]) return;
    int d = g.dst[z][i];
    if (d < EXER_N) return;
    int dl = d - EXER_N;
    int slot = atomicAdd(&g.cnt[z][dl], 1);
    if (slot < CAP) g.adj[z][(size_t)dl * CAP + slot] = g.src[z][i];
}
__global__ void bz_kernel(const float* __restrict__ gb, const float* __restrict__ fcW,
                          const float* __restrict__ fcb, float* __restrict__ bz) {
    int p = blockIdx.x, n = threadIdx.x;
    const float* g = gb + (size_t)p * HD;
    const float* W = fcW + (size_t)p * HD * DD;
    float s = fcb[(size_t)p * DD + n];
    for (int k = 0; k < HD; k++) s += g[k] * W[(size_t)k * DD + n];
    bz[(size_t)p * DD + n] = s;
}
__global__ void el_er_b(EEB g) {
    int z = blockIdx.y;
    int n = blockIdx.x, t = threadIdx.x;
    const float* fr = g.f[z] + (size_t)n * HD;
    const float* al = g.al[z];
    const float* ar = g.ar[z];
    float pel[3], per[3];
#pragma unroll
    for (int h = 0; h < 3; h++) {
        float v = fr[h * DD + t];
        pel[h] = v * al[h * DD + t];
        per[h] = v * ar[h * DD + t];
    }
#pragma unroll
    for (int off = 16; off; off >>= 1) {
#pragma unroll
        for (int h = 0; h < 3; h++) {
            pel[h] += __shfl_xor_sync(0xffffffffu, pel[h], off);
            per[h] += __shfl_xor_sync(0xffffffffu, per[h], off);
        }
    }
    __shared__ float red[4][6];
    int w = t >> 5;
    if ((t & 31) == 0) {
#pragma unroll
        for (int h = 0; h < 3; h++) { red[w][h] = pel[h]; red[w][3 + h] = per[h]; }
    }
    __syncthreads();
    if (t < 6) {
        float v = red[0][t] + red[1][t] + red[2][t] + red[3][t];
        if (t < 3) g.el[z][(size_t)n * 3 + t] = v;
        else       g.er[z][(size_t)n * 3 + (t - 3)] = v;
    }
}
__global__ void zlzr_b(ZZB g) {
    int z = blockIdx.y;
    int n = blockIdx.x, t = threadIdx.x;
    float v = g.z[z][(size_t)n * DD + t];
    float a = v * g.aW[z][t];
    float b = v * g.aW[z][DD + t];
#pragma unroll
    for (int off = 16; off; off >>= 1) {
        a += __shfl_xor_sync(0xffffffffu, a, off);
        b += __shfl_xor_sync(0xffffffffu, b, off);
    }
    __shared__ float red[4][2];
    int w = t >> 5;
    if ((t & 31) == 0) { red[w][0] = a; red[w][1] = b; }
    __syncthreads();
    if (t < 2) {
        float v2 = red[0][t] + red[1][t] + red[2][t] + red[3][t];
        if (t == 0) g.zl[z][n] = v2; else g.zr[z][n] = v2;
    }
}
__global__ void attn1_b(A1B g) {
    int z = blockIdx.y;
    int dl = blockIdx.x, t = threadIdx.x;
    int deg = g.cnt[z][dl]; if (deg > CAP) deg = CAP;
    const float* elE = g.elE[z];
    const float* elS = g.elS[z];
    const float* fE  = g.fE[z];
    const float* fS  = g.fS[z];
    __shared__ int   ssrc[CAP];
    __shared__ float se[CAP * 3];
    __shared__ float sm[3], ssum[3];
    float er0 = g.erS[z][(size_t)dl * 3 + 0];
    float er1 = g.erS[z][(size_t)dl * 3 + 1];
    float er2 = g.erS[z][(size_t)dl * 3 + 2];
    if (t < deg) {
        int s = g.adj[z][(size_t)dl * CAP + t];
        ssrc[t] = s;
        const float* el = (s < EXER_N) ? (elE + (size_t)s * 3) : (elS + (size_t)(s - EXER_N) * 3);
        float e0 = el[0] + er0, e1 = el[1] + er1, e2 = el[2] + er2;
        se[t * 3 + 0] = e0 > 0.f ? e0 : 0.2f * e0;
        se[t * 3 + 1] = e1 > 0.f ? e1 : 0.2f * e1;
        se[t * 3 + 2] = e2 > 0.f ? e2 : 0.2f * e2;
    }
    __syncthreads();
    int w = t >> 5, lane = t & 31;
    if (w < 3) {
        float m = -3.0e38f;
        for (int j = lane; j < deg; j += 32) m = fmaxf(m, se[j * 3 + w]);
#pragma unroll
        for (int off = 16; off; off >>= 1) m = fmaxf(m, __shfl_xor_sync(0xffffffffu, m, off));
        float s = 0.f;
        for (int j = lane; j < deg; j += 32) s += expf(se[j * 3 + w] - m);
#pragma unroll
        for (int off = 16; off; off >>= 1) s += __shfl_xor_sync(0xffffffffu, s, off);
        if (lane == 0) { sm[w] = m; ssum[w] = s; }
    }
    __syncthreads();
    if (t < deg) {
#pragma unroll
        for (int h = 0; h < 3; h++)
            se[t * 3 + h] = expf(se[t * 3 + h] - sm[h]) / ssum[h];
    }
    __syncthreads();
    float a0 = 0.f, a1 = 0.f, a2 = 0.f;
    for (int j = 0; j < deg; j++) {
        int s = ssrc[j];
        const float* fr = (s < EXER_N) ? (fE + (size_t)s * HD) : (fS + (size_t)(s - EXER_N) * HD);
        float w0 = se[j * 3 + 0], w1 = se[j * 3 + 1], w2 = se[j * 3 + 2];
        a0 += w0 * fr[t];
        a1 += w1 * fr[DD + t];
        a2 += w2 * fr[2 * DD + t];
    }
    size_t o = (size_t)dl * HD;
    float* rst = g.rst[z];
    rst[o + t] = a0; rst[o + DD + t] = a1; rst[o + 2 * DD + t] = a2;
}
__global__ void attn2_b(A2B g, int ldo) {
    int z = blockIdx.y;
    int dl = blockIdx.x, t = threadIdx.x;
    int deg = g.cnt[z][dl]; if (deg > CAP) deg = CAP;
    const float* zlE = g.zlE[z];
    const float* zlS = g.zlS[z];
    const float* zE  = g.zE[z];
    const float* zS  = g.zS[z];
    __shared__ int   ssrc[CAP];
    __shared__ float se[CAP];
    __shared__ float smx, ssm;
    float zr = g.zrS[z][dl];
    if (t < deg) {
        int s = g.adj[z][(size_t)dl * CAP + t];
        ssrc[t] = s;
        float zl = (s < EXER_N) ? zlE[s] : zlS[s - EXER_N];
        se[t] = zl + zr;
    }
    __syncthreads();
    if (t < 32) {
        float m = -3.0e38f;
        for (int j = t; j < deg; j += 32) m = fmaxf(m, se[j]);
#pragma unroll
        for (int off = 16; off; off >>= 1) m = fmaxf(m, __shfl_xor_sync(0xffffffffu, m, off));
        float s = 0.f;
        for (int j = t; j < deg; j += 32) s += expf(se[j] - m);
#pragma unroll
        for (int off = 16; off; off >>= 1) s += __shfl_xor_sync(0xffffffffu, s, off);
        if (t == 0) { smx = m; ssm = s; }
    }
    __syncthreads();
    if (t < deg) se[t] = expf(se[t] - smx) / ssm;
    __syncthreads();
    float acc = 0.f;
    for (int j = 0; j < deg; j++) {
        int s = ssrc[j];
        const float* zrow = (s < EXER_N) ? (zE + (size_t)s * DD) : (zS + (size_t)(s - EXER_N) * DD);
        acc += se[j] * zrow[t];
    }
    g.out[z][(size_t)dl * ldo + t] = acc;
    if (g.out2[z]) g.out2[z][(size_t)dl * ldo + t] = acc;
}

// SSL ------------------------------------------------------------------------
__global__ void norm_rows_b(NRB g, const int* __restrict__ ids) {
    int z = blockIdx.y;
    int i = blockIdx.x, t = threadIdx.x;
    int r = ids[i];
    float v = g.emb[z][(size_t)r * DD + t];
    float sq = v * v;
#pragma unroll
    for (int off = 16; off; off >>= 1) sq += __shfl_xor_sync(0xffffffffu, sq, off);
    __shared__ float w4[4];
    if ((t & 31) == 0) w4[t >> 5] = sq;
    __syncthreads();
    float tot = w4[0] + w4[1] + w4[2] + w4[3];
    float nrm = sqrtf(tot);
    g.out[z][(size_t)i * DD + t] = v / fmaxf(nrm, 1e-12f);
}
__global__ void colsum(const float* __restrict__ nbp, float* __restrict__ S) {
    int t = threadIdx.x;
    float s = 0.f;
    for (int i = 0; i < BATCH; i++) s += nbp[(size_t)i * DD + t];
    S[t] = s;
}
__global__ void loss_kernel(const float* __restrict__ nb, const float* __restrict__ nbp,
                            const float* __restrict__ S, float* __restrict__ out) {
    int t = threadIdx.x;
    float lsum = 0.f;
    for (int i = t; i < BATCH; i += 256) {
        const float* x = nb  + (size_t)i * DD;
        const float* y = nbp + (size_t)i * DD;
        float dg = 0.f, rs = 0.f;
        for (int d = 0; d < DD; d++) {
            float xv = x[d];
            dg += xv * y[d];
            rs += xv * S[d];
        }
        float divided = expf(dg * 5.0f) / (rs * 5.0f + 1e-8f);
        lsum += -logf(fmaxf(divided, 1e-8f));
    }
    __shared__ float red[256];
    red[t] = lsum;
    __syncthreads();
    for (int s = 128; s; s >>= 1) { if (t < s) red[t] += red[t + s]; __syncthreads(); }
    if (t == 0) out[0] = red[0];
}

// ---------------- host orchestration ------------------------------------------
extern "C" void kernel_launch(void* const* d_in, const int* in_sizes, int n_in,
                              void* d_out_, int out_size)
{
    const float* stu_table  = (const float*)d_in[0];
    const float* exer_table = (const float*)d_in[1];
    const float* gat_W  = (const float*)d_in[2];
    const float* attn_l = (const float*)d_in[3];
    const float* attn_r = (const float*)d_in[4];
    const float* gat_b  = (const float*)d_in[5];
    const float* fc_W   = (const float*)d_in[6];
    const float* fc_b   = (const float*)d_in[7];
    const float* aW     = (const float*)d_in[8];
    const float* f1W    = (const float*)d_in[9];
    const float* f1b    = (const float*)d_in[10];
    const float* f2W    = (const float*)d_in[11];
    const float* f2b    = (const float*)d_in[12];
    const int* e_src[3] = {(const int*)d_in[13], (const int*)d_in[15], (const int*)d_in[21]};
    const int* e_dst[3] = {(const int*)d_in[14], (const int*)d_in[16], (const int*)d_in[22]};
    int e_n[3] = {in_sizes[13], in_sizes[15], in_sizes[21]};
    const int* stu_id = (const int*)d_in[23];
    float* d_out = (float*)d_out_;
    (void)n_in;

    float* FA = nullptr; int* IA = nullptr;
    cudaGetSymbolAddress((void**)&FA, g_farena);
    cudaGetSymbolAddress((void**)&IA, g_iarena);

    float* fE    = FA + O_fE;
    float* elE   = FA + O_elE;
    float* erD   = FA + O_erD;
    float* zE    = FA + O_zE;
    float* zlE   = FA + O_zlE;
    float* zrD   = FA + O_zrD;
    float* bz    = FA + O_bz;
    float* ABCD  = FA + O_ABCD;
    float* ABPCD = FA + O_ABPCD;
    float* stu1  = FA + O_stu1;
    float* stu1p = FA + O_stu1p;
    float* XYX   = FA + O_XYX;
    float* XYP   = FA + O_XYP;
    float* stu2  = FA + O_stu2;
    float* stu2p = FA + O_stu2p;
    float* nb    = FA + O_nb;
    float* nbp   = FA + O_nbp;
    float* Sv    = FA + O_S;
    float* lossD = FA + O_lossd;

    const int pidx[3] = {0, 1, 4};
    const int gM_E = (EXER_N + 63) / 64;
    const int gM_S = (STU_N + 63) / 64;

    auto scr  = [&](int sc, size_t off) { return FA + O_SCR + (size_t)sc * SC_TOT + off; };
    auto adjP = [&](int s) { return IA + OI_adj + (size_t)s * STU_N * CAP; };
    auto cntP = [&](int s) { return IA + OI_cnt + (size_t)s * STU_N; };

    // ---- bias precompute + adjacency ----
    bz_kernel<<<5, 128>>>(gat_b, fc_W, fc_b, bz);
    zero_int<<<(3 * STU_N + 255) / 256, 256>>>(IA + OI_cnt, 3 * STU_N);
    {
        ADJB g{};
        int max_e = 0;
        for (int s = 0; s < 3; s++) {
            g.src[s] = e_src[s]; g.dst[s] = e_dst[s]; g.ecnt[s] = e_n[s];
            g.adj[s] = adjP(s);  g.cnt[s] = cntP(s);
            if (e_n[s] > max_e) max_e = e_n[s];
        }
        build_adj_b<<<dim3((max_e + 255) / 256, 3), 256>>>(g);
    }

    // ---- phase A: exer-side invariants (batched z=3) ----
    {
        GB g{};
        for (int s = 0; s < 3; s++) {
            g.A[s] = exer_table;
            g.B[s] = gat_W + (size_t)pidx[s] * DD * HD;
            g.C[s] = fE + (size_t)s * EXER_N * HD;
        }
        sgemm_b<<<dim3(HD / 64, gM_E, 3), 256>>>(g, DD, HD, 0, EXER_N, HD, DD);
    }
    {
        EEB g{};
        for (int s = 0; s < 3; s++) {
            g.f[s]  = fE + (size_t)s * EXER_N * HD;
            g.al[s] = attn_l + (size_t)pidx[s] * HD;
            g.ar[s] = attn_r + (size_t)pidx[s] * HD;
            g.el[s] = elE + (size_t)s * EXER_N * 3;
            g.er[s] = erD;
        }
        el_er_b<<<dim3(EXER_N, 3), 128>>>(g);
    }
    {
        GB g{};
        for (int s = 0; s < 3; s++) {
            g.A[s] = fE + (size_t)s * EXER_N * HD;
            g.B[s] = fc_W + (size_t)pidx[s] * HD * DD;
            g.C[s] = zE + (size_t)s * EXER_N * DD;
            g.bias[s] = bz + (size_t)pidx[s] * DD;
        }
        sgemm_b<<<dim3(DD / 64, gM_E, 3), 256>>>(g, HD, DD, 0, EXER_N, DD, HD);
    }
    {
        ZZB g{};
        for (int s = 0; s < 3; s++) {
            g.z[s]  = zE + (size_t)s * EXER_N * DD;
            g.aW[s] = aW + (size_t)pidx[s] * 2 * DD;
            g.zl[s] = zlE + (size_t)s * EXER_N;
            g.zr[s] = zrD;
        }
        zlzr_b<<<dim3(EXER_N, 3), 128>>>(g);
    }

    // ---- layers 2,3 (self-loop only), batched z=2, dual-store into ABCD+ABPCD --
    {
        GB g{};
        for (int i = 0; i < 2; i++) {
            g.A[i] = stu_table;
            g.B[i] = gat_W + (size_t)(2 + i) * DD * HD;
            g.C[i] = scr(i, SC_fS);
        }
        sgemm_b<<<dim3(HD / 64, gM_S, 2), 256>>>(g, DD, HD, 0, STU_N, HD, DD);
    }
    {
        GB g{};
        for (int i = 0; i < 2; i++) {
            int coff = (i == 0) ? 2 * DD : 3 * DD;
            g.A[i] = scr(i, SC_fS);
            g.B[i] = fc_W + (size_t)(2 + i) * HD * DD;
            g.C[i] = ABCD + coff;
            g.C2[i] = ABPCD + coff;
            g.bias[i] = bz + (size_t)(2 + i) * DD;
        }
        sgemm_b<<<dim3(DD / 64, gM_S, 2), 256>>>(g, HD, 4 * DD, 0, STU_N, DD, HD);
    }

    // ---- batched run_gat: nz instances, slot[i], input xS[i], out/out2/ldo ----
    auto run_gat_batch = [&](int nz, const int* slot, const float* const* xS,
                             float* const* outb, float* const* outb2, int ldo) {
        {
            GB g{};
            for (int i = 0; i < nz; i++) {
                g.A[i] = xS[i];
                g.B[i] = gat_W + (size_t)pidx[slot[i]] * DD * HD;
                g.C[i] = scr(i, SC_fS);
            }
            sgemm_b<<<dim3(HD / 64, gM_S, nz), 256>>>(g, DD, HD, 0, STU_N, HD, DD);
        }
        {
            EEB g{};
            for (int i = 0; i < nz; i++) {
                g.f[i]  = scr(i, SC_fS);
                g.al[i] = attn_l + (size_t)pidx[slot[i]] * HD;
                g.ar[i] = attn_r + (size_t)pidx[slot[i]] * HD;
                g.el[i] = scr(i, SC_elS);
                g.er[i] = scr(i, SC_erS);
            }
            el_er_b<<<dim3(STU_N, nz), 128>>>(g);
        }
        {
            A1B g{};
            for (int i = 0; i < nz; i++) {
                int s = slot[i];
                g.adj[i] = adjP(s); g.cnt[i] = cntP(s);
                g.elE[i] = elE + (size_t)s * EXER_N * 3;
                g.elS[i] = scr(i, SC_elS);
                g.erS[i] = scr(i, SC_erS);
                g.fE[i]  = fE + (size_t)s * EXER_N * HD;
                g.fS[i]  = scr(i, SC_fS);
                g.rst[i] = scr(i, SC_rst);
            }
            attn1_b<<<dim3(STU_N, nz), 128>>>(g);
        }
        {
            GB g{};
            for (int i = 0; i < nz; i++) {
                g.A[i] = scr(i, SC_rst);
                g.B[i] = fc_W + (size_t)pidx[slot[i]] * HD * DD;
                g.C[i] = scr(i, SC_zS);
                g.bias[i] = bz + (size_t)pidx[slot[i]] * DD;
            }
            sgemm_b<<<dim3(DD / 64, gM_S, nz), 256>>>(g, HD, DD, 0, STU_N, DD, HD);
        }
        {
            ZZB g{};
            for (int i = 0; i < nz; i++) {
                g.z[i]  = scr(i, SC_zS);
                g.aW[i] = aW + (size_t)pidx[slot[i]] * 2 * DD;
                g.zl[i] = scr(i, SC_zlS);
                g.zr[i] = scr(i, SC_zrS);
            }
            zlzr_b<<<dim3(STU_N, nz), 128>>>(g);
        }
        {
            A2B g{};
            for (int i = 0; i < nz; i++) {
                int s = slot[i];
                g.adj[i] = adjP(s); g.cnt[i] = cntP(s);
                g.zlE[i] = zlE + (size_t)s * EXER_N;
                g.zlS[i] = scr(i, SC_zlS);
                g.zrS[i] = scr(i, SC_zrS);
                g.zE[i]  = zE + (size_t)s * EXER_N * DD;
                g.zS[i]  = scr(i, SC_zS);
                g.out[i]  = outb[i];
                g.out2[i] = outb2 ? outb2[i] : nullptr;
            }
            attn2_b<<<dim3(STU_N, nz), 128>>>(g, ldo);
        }
    };

    // ---- phase B: round-1 GAT (a, b, bp), batched z=3 ----
    {
        const int slot[3] = {0, 1, 2};
        const float* xS[3]  = {stu_table, stu_table, stu_table};
        float* outb[3]  = {ABCD, ABCD + DD, ABPCD + DD};
        float* outb2[3] = {ABPCD, nullptr, nullptr};       // a dual-stored
        run_gat_batch(3, slot, xS, outb, outb2, 4 * DD);
    }

    // ---- fuse1: K=512 GEMM + residual, batched z=2 ----
    {
        GB g{};
        g.A[0] = ABCD;  g.C[0] = stu1;  g.bias[0] = f1b; g.addm[0] = stu_table;
        g.A[1] = ABPCD; g.C[1] = stu1p; g.bias[1] = f1b; g.addm[1] = stu_table;
        g.B[0] = f1W; g.B[1] = f1W;
        sgemm_b<<<dim3(DD / 64, gM_S, 2), 256>>>(g, 4 * DD, DD, DD, STU_N, DD, 4 * DD);
    }

    // ---- phase D: expr2 on both branches, batched z=4 ----
    {
        const int slot[4] = {0, 1, 0, 1};
        const float* xS[4] = {stu1, stu1, stu1p, stu1p};
        float* outb[4] = {XYX, XYX + DD, XYP, XYP + DD};
        run_gat_batch(4, slot, xS, outb, nullptr, 2 * DD);
    }

    // ---- fusion2: K=256 + residual, batched z=2 ----
    {
        GB g{};
        g.A[0] = XYX; g.C[0] = stu2;  g.bias[0] = f2b; g.addm[0] = stu1;
        g.A[1] = XYP; g.C[1] = stu2p; g.bias[1] = f2b; g.addm[1] = stu1p;
        g.B[0] = f2W; g.B[1] = f2W;
        sgemm_b<<<dim3(DD / 64, gM_S, 2), 256>>>(g, 2 * DD, DD, DD, STU_N, DD, 2 * DD);
    }

    // ---- outputs ----
    const int NOUT = STU_N * DD;
    if (out_size >= NOUT)
        copy_f<<<(NOUT + 255) / 256, 256>>>(stu2, d_out, NOUT);

    float* lossdst = lossD;
    if (out_size == 1) lossdst = d_out;
    else if (out_size > NOUT) lossdst = d_out + (out_size - 1);

    {
        NRB g{};
        g.emb[0] = stu2;  g.out[0] = nb;
        g.emb[1] = stu2p; g.out[1] = nbp;
        norm_rows_b<<<dim3(BATCH, 2), 128>>>(g, stu_id);
    }
    colsum<<<1, 128>>>(nbp, Sv);
    loss_kernel<<<1, 256>>>(nb, nbp, Sv, lossdst);
}

// round 5
// speedup vs baseline: 1.5053x; 1.3613x over previous
#include <cuda_runtime.h>
#include <math.h>
#include <stdint.h>

#define EXER_N 10000
#define STU_N  20000
#define DD     128
#define HH     3
#define HD     384
#define CAP    96
#define BATCH  2048

#define SZF(x) ((size_t)(x))

// ---------------- scratch arena ---------------------------------------------
static constexpr size_t O_fE    = 0;                                    // 3*EXER_N*HD
static constexpr size_t O_elE   = O_fE    + SZF(3)*EXER_N*HD;
static constexpr size_t O_erD   = O_elE   + SZF(3)*EXER_N*3;            // dump
static constexpr size_t O_zE    = O_erD   + SZF(EXER_N)*3;
static constexpr size_t O_zlE   = O_zE    + SZF(3)*EXER_N*DD;
static constexpr size_t O_zrD   = O_zlE   + SZF(3)*EXER_N;              // dump
static constexpr size_t O_bz    = O_zrD   + SZF(EXER_N);
static constexpr size_t O_ABCD  = O_bz    + SZF(5)*DD;                  // 20000x512
static constexpr size_t O_ABPCD = O_ABCD  + SZF(STU_N)*4*DD;            // 20000x512
static constexpr size_t O_stu1  = O_ABPCD + SZF(STU_N)*4*DD;
static constexpr size_t O_stu1p = O_stu1  + SZF(STU_N)*DD;
static constexpr size_t O_XYX   = O_stu1p + SZF(STU_N)*DD;              // 20000x256
static constexpr size_t O_XYP   = O_XYX   + SZF(STU_N)*2*DD;            // 20000x256
static constexpr size_t O_stu2  = O_XYP   + SZF(STU_N)*2*DD;
static constexpr size_t O_stu2p = O_stu2  + SZF(STU_N)*DD;
static constexpr size_t O_nb    = O_stu2p + SZF(STU_N)*DD;
static constexpr size_t O_nbp   = O_nb    + SZF(BATCH)*DD;
static constexpr size_t O_S     = O_nbp   + SZF(BATCH)*DD;
static constexpr size_t O_lossd = O_S     + DD;
static constexpr size_t O_SCR   = O_lossd + 16;
// per-instance scratch set (x4)
static constexpr size_t SC_fS   = 0;                                    // STU_N*HD
static constexpr size_t SC_elS  = SC_fS  + SZF(STU_N)*HD;
static constexpr size_t SC_erS  = SC_elS + SZF(STU_N)*3;
static constexpr size_t SC_rst  = SC_erS + SZF(STU_N)*3;
static constexpr size_t SC_zS   = SC_rst + SZF(STU_N)*HD;
static constexpr size_t SC_zlS  = SC_zS  + SZF(STU_N)*DD;
static constexpr size_t SC_zrS  = SC_zlS + SZF(STU_N);
static constexpr size_t SC_TOT  = SC_zrS + SZF(STU_N);
static constexpr size_t F_TOT   = O_SCR + 4*SC_TOT;

static constexpr size_t OI_adj  = 0;                                    // 3*STU_N*CAP
static constexpr size_t OI_cnt  = SZF(3)*STU_N*CAP;
static constexpr size_t I_TOT   = OI_cnt + SZF(3)*STU_N;

__device__ __align__(256) float g_farena[F_TOT];
__device__ __align__(256) int   g_iarena[I_TOT];

// ---------------- batched pointer structs ------------------------------------
struct GB {
    const float* A[4];
    const float* B[4];
    float*       C[4];
    float*       C2[4];
    const float* bias[4];
    const float* addm[4];
};
struct EEB {
    const float* f[4];
    const float* al[4];
    const float* ar[4];
    float*       el[4];
    float*       er[4];
};
struct ZZB {
    const float* z[4];
    const float* aW[4];
    float*       zl[4];
    float*       zr[4];
};
struct A1B {
    const int*   adj[4];
    const int*   cnt[4];
    const float* elE[4];
    const float* elS[4];
    const float* erS[4];
    const float* fE[4];
    const float* fS[4];
    float*       rst[4];
};
struct A2B {
    const int*   adj[4];
    const int*   cnt[4];
    const float* zlE[4];
    const float* zlS[4];
    const float* zrS[4];
    const float* zE[4];
    const float* zS[4];
    float*       out[4];
    float*       out2[4];
};
struct ADJB {
    const int* src[3];
    const int* dst[3];
    int        ecnt[3];
    int*       adj[3];
    int*       cnt[3];
};
struct NRB {
    const float* emb[2];
    float*       out[2];
};

// ---------------- TF32 tensor-core batched GEMM ------------------------------
// C = A[MxK](lda) @ B[KxN] (+bias)(+addm), fp32 accumulate, tf32 inputs.
// 128x128 block tile, BK=16, 256 threads = 8 warps (4m x 2n), warp tile 32x64.
// mma.sync.aligned.m16n8k8.row.col.f32.tf32.tf32.f32
// Requires: N % 128 == 0, K % 16 == 0. M arbitrary.

__device__ __forceinline__ uint32_t f2tf32(float x) {
    uint32_t u;
    asm("cvt.rna.tf32.f32 %0, %1;" : "=r"(u) : "f"(x));
    return u;
}
__device__ __forceinline__ void mma_tf32(float* c, uint32_t a0, uint32_t a1,
                                         uint32_t a2, uint32_t a3,
                                         uint32_t b0, uint32_t b1) {
    asm volatile(
        "mma.sync.aligned.m16n8k8.row.col.f32.tf32.tf32.f32 "
        "{%0,%1,%2,%3}, {%4,%5,%6,%7}, {%8,%9}, {%0,%1,%2,%3};"
        : "+f"(c[0]), "+f"(c[1]), "+f"(c[2]), "+f"(c[3])
        : "r"(a0), "r"(a1), "r"(a2), "r"(a3), "r"(b0), "r"(b1));
}

#define SPAD 132   // padded row stride (floats) for both smem tiles

__global__ __launch_bounds__(256)
void tgemm_b(GB g, int lda, int ldc, int ldadd, int M, int N, int K)
{
    const int z = blockIdx.z;
    const float* __restrict__ A    = g.A[z];
    const float* __restrict__ B    = g.B[z];
    float*       __restrict__ C    = g.C[z];
    float*                    C2   = g.C2[z];
    const float*              bias = g.bias[z];
    const float*              addm = g.addm[z];

    __shared__ uint32_t As[16][SPAD];
    __shared__ uint32_t Bs[16][SPAD];

    const int tid  = threadIdx.x;
    const int bm   = blockIdx.y * 128;
    const int bn   = blockIdx.x * 128;
    const int lane = tid & 31;
    const int gid  = lane >> 2;       // 0..7
    const int tg   = lane & 3;        // 0..3
    const int warp = tid >> 5;
    const int wm   = warp & 3;        // 0..3 -> m offset wm*32
    const int wn   = warp >> 2;       // 0..1 -> n offset wn*64

    float acc[2][8][4];
#pragma unroll
    for (int mt = 0; mt < 2; mt++)
#pragma unroll
        for (int nt = 0; nt < 8; nt++)
#pragma unroll
            for (int c = 0; c < 4; c++) acc[mt][nt][c] = 0.f;

    // gmem staging indices
    const int am  = tid >> 1;            // 0..127 (A row within tile)
    const int ak0 = (tid & 1) * 4;       // 0 or 4
    const int brr = tid >> 5;            // 0..7 (B row)
    const int bcc = (tid & 31) * 4;      // 0..124

    for (int k0 = 0; k0 < K; k0 += 16) {
        // stage gmem -> regs
        float4 av0, av1, bv0, bv1;
        const bool arow_ok = (bm + am < M);
        av0 = arow_ok ? *(const float4*)(A + (size_t)(bm + am) * lda + k0 + ak0)
                      : make_float4(0.f, 0.f, 0.f, 0.f);
        av1 = arow_ok ? *(const float4*)(A + (size_t)(bm + am) * lda + k0 + 8 + ak0)
                      : make_float4(0.f, 0.f, 0.f, 0.f);
        bv0 = *(const float4*)(B + (size_t)(k0 + brr) * N + bn + bcc);
        bv1 = *(const float4*)(B + (size_t)(k0 + 8 + brr) * N + bn + bcc);

        __syncthreads();   // previous tile fully consumed
        As[ak0 + 0][am] = f2tf32(av0.x);
        As[ak0 + 1][am] = f2tf32(av0.y);
        As[ak0 + 2][am] = f2tf32(av0.z);
        As[ak0 + 3][am] = f2tf32(av0.w);
        As[8 + ak0 + 0][am] = f2tf32(av1.x);
        As[8 + ak0 + 1][am] = f2tf32(av1.y);
        As[8 + ak0 + 2][am] = f2tf32(av1.z);
        As[8 + ak0 + 3][am] = f2tf32(av1.w);
        Bs[brr][bcc + 0] = f2tf32(bv0.x);
        Bs[brr][bcc + 1] = f2tf32(bv0.y);
        Bs[brr][bcc + 2] = f2tf32(bv0.z);
        Bs[brr][bcc + 3] = f2tf32(bv0.w);
        Bs[8 + brr][bcc + 0] = f2tf32(bv1.x);
        Bs[8 + brr][bcc + 1] = f2tf32(bv1.y);
        Bs[8 + brr][bcc + 2] = f2tf32(bv1.z);
        Bs[8 + brr][bcc + 3] = f2tf32(bv1.w);
        __syncthreads();

#pragma unroll
        for (int ks = 0; ks < 2; ks++) {
            const int kk = ks * 8;
            uint32_t bf[8][2];
#pragma unroll
            for (int nt = 0; nt < 8; nt++) {
                const int n0 = wn * 64 + nt * 8 + gid;
                bf[nt][0] = Bs[kk + tg][n0];
                bf[nt][1] = Bs[kk + tg + 4][n0];
            }
#pragma unroll
            for (int mt = 0; mt < 2; mt++) {
                const int m0 = wm * 32 + mt * 16;
                uint32_t a0 = As[kk + tg][m0 + gid];
                uint32_t a1 = As[kk + tg][m0 + gid + 8];
                uint32_t a2 = As[kk + tg + 4][m0 + gid];
                uint32_t a3 = As[kk + tg + 4][m0 + gid + 8];
#pragma unroll
                for (int nt = 0; nt < 8; nt++)
                    mma_tf32(acc[mt][nt], a0, a1, a2, a3, bf[nt][0], bf[nt][1]);
            }
        }
    }

    // epilogue: c0,c1 -> row gid, cols tg*2, tg*2+1 ; c2,c3 -> row gid+8
#pragma unroll
    for (int mt = 0; mt < 2; mt++) {
        const int r0 = bm + wm * 32 + mt * 16 + gid;
        const int r1 = r0 + 8;
#pragma unroll
        for (int nt = 0; nt < 8; nt++) {
            const int n = bn + wn * 64 + nt * 8 + tg * 2;
            float2 v0 = make_float2(acc[mt][nt][0], acc[mt][nt][1]);
            float2 v1 = make_float2(acc[mt][nt][2], acc[mt][nt][3]);
            if (bias) {
                float b0 = bias[n], b1 = bias[n + 1];
                v0.x += b0; v0.y += b1;
                v1.x += b0; v1.y += b1;
            }
            if (r0 < M) {
                float2 o = v0;
                if (addm) {
                    const float2 ad = *(const float2*)(addm + (size_t)r0 * ldadd + n);
                    o.x += ad.x; o.y += ad.y;
                }
                *(float2*)(C + (size_t)r0 * ldc + n) = o;
                if (C2) *(float2*)(C2 + (size_t)r0 * ldc + n) = o;
            }
            if (r1 < M) {
                float2 o = v1;
                if (addm) {
                    const float2 ad = *(const float2*)(addm + (size_t)r1 * ldadd + n);
                    o.x += ad.x; o.y += ad.y;
                }
                *(float2*)(C + (size_t)r1 * ldc + n) = o;
                if (C2) *(float2*)(C2 + (size_t)r1 * ldc + n) = o;
            }
        }
    }
}

// ---------------- small batched kernels ---------------------------------------
__global__ void zero_int(int* p, int n) {
    int i = blockIdx.x * blockDim.x + threadIdx.x;
    if (i < n) p[i] = 0;
}
__global__ void copy_f(const float* __restrict__ s, float* __restrict__ d, int n) {
    int i = blockIdx.x * blockDim.x + threadIdx.x;
    if (i < n) d[i] = s[i];
}
__global__ void build_adj_b(ADJB g) {
    int z = blockIdx.y;
    int i = blockIdx.x * blockDim.x + threadIdx.x;
    if (i >= g.ecnt[z]) return;
    int d = g.dst[z][i];
    if (d < EXER_N) return;
    int dl = d - EXER_N;
    int slot = atomicAdd(&g.cnt[z][dl], 1);
    if (slot < CAP) g.adj[z][(size_t)dl * CAP + slot] = g.src[z][i];
}
__global__ void bz_kernel(const float* __restrict__ gb, const float* __restrict__ fcW,
                          const float* __restrict__ fcb, float* __restrict__ bz) {
    int p = blockIdx.x, n = threadIdx.x;
    const float* g = gb + (size_t)p * HD;
    const float* W = fcW + (size_t)p * HD * DD;
    float s = fcb[(size_t)p * DD + n];
    for (int k = 0; k < HD; k++) s += g[k] * W[(size_t)k * DD + n];
    bz[(size_t)p * DD + n] = s;
}
__global__ void el_er_b(EEB g) {
    int z = blockIdx.y;
    int n = blockIdx.x, t = threadIdx.x;
    const float* fr = g.f[z] + (size_t)n * HD;
    const float* al = g.al[z];
    const float* ar = g.ar[z];
    float pel[3], per[3];
#pragma unroll
    for (int h = 0; h < 3; h++) {
        float v = fr[h * DD + t];
        pel[h] = v * al[h * DD + t];
        per[h] = v * ar[h * DD + t];
    }
#pragma unroll
    for (int off = 16; off; off >>= 1) {
#pragma unroll
        for (int h = 0; h < 3; h++) {
            pel[h] += __shfl_xor_sync(0xffffffffu, pel[h], off);
            per[h] += __shfl_xor_sync(0xffffffffu, per[h], off);
        }
    }
    __shared__ float red[4][6];
    int w = t >> 5;
    if ((t & 31) == 0) {
#pragma unroll
        for (int h = 0; h < 3; h++) { red[w][h] = pel[h]; red[w][3 + h] = per[h]; }
    }
    __syncthreads();
    if (t < 6) {
        float v = red[0][t] + red[1][t] + red[2][t] + red[3][t];
        if (t < 3) g.el[z][(size_t)n * 3 + t] = v;
        else       g.er[z][(size_t)n * 3 + (t - 3)] = v;
    }
}
__global__ void zlzr_b(ZZB g) {
    int z = blockIdx.y;
    int n = blockIdx.x, t = threadIdx.x;
    float v = g.z[z][(size_t)n * DD + t];
    float a = v * g.aW[z][t];
    float b = v * g.aW[z][DD + t];
#pragma unroll
    for (int off = 16; off; off >>= 1) {
        a += __shfl_xor_sync(0xffffffffu, a, off);
        b += __shfl_xor_sync(0xffffffffu, b, off);
    }
    __shared__ float red[4][2];
    int w = t >> 5;
    if ((t & 31) == 0) { red[w][0] = a; red[w][1] = b; }
    __syncthreads();
    if (t < 2) {
        float v2 = red[0][t] + red[1][t] + red[2][t] + red[3][t];
        if (t == 0) g.zl[z][n] = v2; else g.zr[z][n] = v2;
    }
}
__global__ void attn1_b(A1B g) {
    int z = blockIdx.y;
    int dl = blockIdx.x, t = threadIdx.x;
    int deg = g.cnt[z][dl]; if (deg > CAP) deg = CAP;
    const float* elE = g.elE[z];
    const float* elS = g.elS[z];
    const float* fE  = g.fE[z];
    const float* fS  = g.fS[z];
    __shared__ int   ssrc[CAP];
    __shared__ float se[CAP * 3];
    __shared__ float sm[3], ssum[3];
    float er0 = g.erS[z][(size_t)dl * 3 + 0];
    float er1 = g.erS[z][(size_t)dl * 3 + 1];
    float er2 = g.erS[z][(size_t)dl * 3 + 2];
    if (t < deg) {
        int s = g.adj[z][(size_t)dl * CAP + t];
        ssrc[t] = s;
        const float* el = (s < EXER_N) ? (elE + (size_t)s * 3) : (elS + (size_t)(s - EXER_N) * 3);
        float e0 = el[0] + er0, e1 = el[1] + er1, e2 = el[2] + er2;
        se[t * 3 + 0] = e0 > 0.f ? e0 : 0.2f * e0;
        se[t * 3 + 1] = e1 > 0.f ? e1 : 0.2f * e1;
        se[t * 3 + 2] = e2 > 0.f ? e2 : 0.2f * e2;
    }
    __syncthreads();
    int w = t >> 5, lane = t & 31;
    if (w < 3) {
        float m = -3.0e38f;
        for (int j = lane; j < deg; j += 32) m = fmaxf(m, se[j * 3 + w]);
#pragma unroll
        for (int off = 16; off; off >>= 1) m = fmaxf(m, __shfl_xor_sync(0xffffffffu, m, off));
        float s = 0.f;
        for (int j = lane; j < deg; j += 32) s += expf(se[j * 3 + w] - m);
#pragma unroll
        for (int off = 16; off; off >>= 1) s += __shfl_xor_sync(0xffffffffu, s, off);
        if (lane == 0) { sm[w] = m; ssum[w] = s; }
    }
    __syncthreads();
    if (t < deg) {
#pragma unroll
        for (int h = 0; h < 3; h++)
            se[t * 3 + h] = expf(se[t * 3 + h] - sm[h]) / ssum[h];
    }
    __syncthreads();
    float a0 = 0.f, a1 = 0.f, a2 = 0.f;
    for (int j = 0; j < deg; j++) {
        int s = ssrc[j];
        const float* fr = (s < EXER_N) ? (fE + (size_t)s * HD) : (fS + (size_t)(s - EXER_N) * HD);
        float w0 = se[j * 3 + 0], w1 = se[j * 3 + 1], w2 = se[j * 3 + 2];
        a0 += w0 * fr[t];
        a1 += w1 * fr[DD + t];
        a2 += w2 * fr[2 * DD + t];
    }
    size_t o = (size_t)dl * HD;
    float* rst = g.rst[z];
    rst[o + t] = a0; rst[o + DD + t] = a1; rst[o + 2 * DD + t] = a2;
}
__global__ void attn2_b(A2B g, int ldo) {
    int z = blockIdx.y;
    int dl = blockIdx.x, t = threadIdx.x;
    int deg = g.cnt[z][dl]; if (deg > CAP) deg = CAP;
    const float* zlE = g.zlE[z];
    const float* zlS = g.zlS[z];
    const float* zE  = g.zE[z];
    const float* zS  = g.zS[z];
    __shared__ int   ssrc[CAP];
    __shared__ float se[CAP];
    __shared__ float smx, ssm;
    float zr = g.zrS[z][dl];
    if (t < deg) {
        int s = g.adj[z][(size_t)dl * CAP + t];
        ssrc[t] = s;
        float zl = (s < EXER_N) ? zlE[s] : zlS[s - EXER_N];
        se[t] = zl + zr;
    }
    __syncthreads();
    if (t < 32) {
        float m = -3.0e38f;
        for (int j = t; j < deg; j += 32) m = fmaxf(m, se[j]);
#pragma unroll
        for (int off = 16; off; off >>= 1) m = fmaxf(m, __shfl_xor_sync(0xffffffffu, m, off));
        float s = 0.f;
        for (int j = t; j < deg; j += 32) s += expf(se[j] - m);
#pragma unroll
        for (int off = 16; off; off >>= 1) s += __shfl_xor_sync(0xffffffffu, s, off);
        if (t == 0) { smx = m; ssm = s; }
    }
    __syncthreads();
    if (t < deg) se[t] = expf(se[t] - smx) / ssm;
    __syncthreads();
    float acc = 0.f;
    for (int j = 0; j < deg; j++) {
        int s = ssrc[j];
        const float* zrow = (s < EXER_N) ? (zE + (size_t)s * DD) : (zS + (size_t)(s - EXER_N) * DD);
        acc += se[j] * zrow[t];
    }
    g.out[z][(size_t)dl * ldo + t] = acc;
    if (g.out2[z]) g.out2[z][(size_t)dl * ldo + t] = acc;
}

// SSL ------------------------------------------------------------------------
__global__ void norm_rows_b(NRB g, const int* __restrict__ ids) {
    int z = blockIdx.y;
    int i = blockIdx.x, t = threadIdx.x;
    int r = ids[i];
    float v = g.emb[z][(size_t)r * DD + t];
    float sq = v * v;
#pragma unroll
    for (int off = 16; off; off >>= 1) sq += __shfl_xor_sync(0xffffffffu, sq, off);
    __shared__ float w4[4];
    if ((t & 31) == 0) w4[t >> 5] = sq;
    __syncthreads();
    float tot = w4[0] + w4[1] + w4[2] + w4[3];
    float nrm = sqrtf(tot);
    g.out[z][(size_t)i * DD + t] = v / fmaxf(nrm, 1e-12f);
}
__global__ void colsum(const float* __restrict__ nbp, float* __restrict__ S) {
    int t = threadIdx.x;
    float s = 0.f;
    for (int i = 0; i < BATCH; i++) s += nbp[(size_t)i * DD + t];
    S[t] = s;
}
__global__ void loss_kernel(const float* __restrict__ nb, const float* __restrict__ nbp,
                            const float* __restrict__ S, float* __restrict__ out) {
    int t = threadIdx.x;
    float lsum = 0.f;
    for (int i = t; i < BATCH; i += 256) {
        const float* x = nb  + (size_t)i * DD;
        const float* y = nbp + (size_t)i * DD;
        float dg = 0.f, rs = 0.f;
        for (int d = 0; d < DD; d++) {
            float xv = x[d];
            dg += xv * y[d];
            rs += xv * S[d];
        }
        float divided = expf(dg * 5.0f) / (rs * 5.0f + 1e-8f);
        lsum += -logf(fmaxf(divided, 1e-8f));
    }
    __shared__ float red[256];
    red[t] = lsum;
    __syncthreads();
    for (int s = 128; s; s >>= 1) { if (t < s) red[t] += red[t + s]; __syncthreads(); }
    if (t == 0) out[0] = red[0];
}

// ---------------- host orchestration ------------------------------------------
extern "C" void kernel_launch(void* const* d_in, const int* in_sizes, int n_in,
                              void* d_out_, int out_size)
{
    const float* stu_table  = (const float*)d_in[0];
    const float* exer_table = (const float*)d_in[1];
    const float* gat_W  = (const float*)d_in[2];
    const float* attn_l = (const float*)d_in[3];
    const float* attn_r = (const float*)d_in[4];
    const float* gat_b  = (const float*)d_in[5];
    const float* fc_W   = (const float*)d_in[6];
    const float* fc_b   = (const float*)d_in[7];
    const float* aW     = (const float*)d_in[8];
    const float* f1W    = (const float*)d_in[9];
    const float* f1b    = (const float*)d_in[10];
    const float* f2W    = (const float*)d_in[11];
    const float* f2b    = (const float*)d_in[12];
    const int* e_src[3] = {(const int*)d_in[13], (const int*)d_in[15], (const int*)d_in[21]};
    const int* e_dst[3] = {(const int*)d_in[14], (const int*)d_in[16], (const int*)d_in[22]};
    int e_n[3] = {in_sizes[13], in_sizes[15], in_sizes[21]};
    const int* stu_id = (const int*)d_in[23];
    float* d_out = (float*)d_out_;
    (void)n_in;

    float* FA = nullptr; int* IA = nullptr;
    cudaGetSymbolAddress((void**)&FA, g_farena);
    cudaGetSymbolAddress((void**)&IA, g_iarena);

    float* fE    = FA + O_fE;
    float* elE   = FA + O_elE;
    float* erD   = FA + O_erD;
    float* zE    = FA + O_zE;
    float* zlE   = FA + O_zlE;
    float* zrD   = FA + O_zrD;
    float* bz    = FA + O_bz;
    float* ABCD  = FA + O_ABCD;
    float* ABPCD = FA + O_ABPCD;
    float* stu1  = FA + O_stu1;
    float* stu1p = FA + O_stu1p;
    float* XYX   = FA + O_XYX;
    float* XYP   = FA + O_XYP;
    float* stu2  = FA + O_stu2;
    float* stu2p = FA + O_stu2p;
    float* nb    = FA + O_nb;
    float* nbp   = FA + O_nbp;
    float* Sv    = FA + O_S;
    float* lossD = FA + O_lossd;

    const int pidx[3] = {0, 1, 4};
    const int gM_E = (EXER_N + 127) / 128;
    const int gM_S = (STU_N + 127) / 128;

    auto scr  = [&](int sc, size_t off) { return FA + O_SCR + (size_t)sc * SC_TOT + off; };
    auto adjP = [&](int s) { return IA + OI_adj + (size_t)s * STU_N * CAP; };
    auto cntP = [&](int s) { return IA + OI_cnt + (size_t)s * STU_N; };

    // ---- bias precompute + adjacency ----
    bz_kernel<<<5, 128>>>(gat_b, fc_W, fc_b, bz);
    zero_int<<<(3 * STU_N + 255) / 256, 256>>>(IA + OI_cnt, 3 * STU_N);
    {
        ADJB g{};
        int max_e = 0;
        for (int s = 0; s < 3; s++) {
            g.src[s] = e_src[s]; g.dst[s] = e_dst[s]; g.ecnt[s] = e_n[s];
            g.adj[s] = adjP(s);  g.cnt[s] = cntP(s);
            if (e_n[s] > max_e) max_e = e_n[s];
        }
        build_adj_b<<<dim3((max_e + 255) / 256, 3), 256>>>(g);
    }

    // ---- phase A: exer-side invariants (batched z=3) ----
    {
        GB g{};
        for (int s = 0; s < 3; s++) {
            g.A[s] = exer_table;
            g.B[s] = gat_W + (size_t)pidx[s] * DD * HD;
            g.C[s] = fE + (size_t)s * EXER_N * HD;
        }
        tgemm_b<<<dim3(HD / 128, gM_E, 3), 256>>>(g, DD, HD, 0, EXER_N, HD, DD);
    }
    {
        EEB g{};
        for (int s = 0; s < 3; s++) {
            g.f[s]  = fE + (size_t)s * EXER_N * HD;
            g.al[s] = attn_l + (size_t)pidx[s] * HD;
            g.ar[s] = attn_r + (size_t)pidx[s] * HD;
            g.el[s] = elE + (size_t)s * EXER_N * 3;
            g.er[s] = erD;
        }
        el_er_b<<<dim3(EXER_N, 3), 128>>>(g);
    }
    {
        GB g{};
        for (int s = 0; s < 3; s++) {
            g.A[s] = fE + (size_t)s * EXER_N * HD;
            g.B[s] = fc_W + (size_t)pidx[s] * HD * DD;
            g.C[s] = zE + (size_t)s * EXER_N * DD;
            g.bias[s] = bz + (size_t)pidx[s] * DD;
        }
        tgemm_b<<<dim3(DD / 128, gM_E, 3), 256>>>(g, HD, DD, 0, EXER_N, DD, HD);
    }
    {
        ZZB g{};
        for (int s = 0; s < 3; s++) {
            g.z[s]  = zE + (size_t)s * EXER_N * DD;
            g.aW[s] = aW + (size_t)pidx[s] * 2 * DD;
            g.zl[s] = zlE + (size_t)s * EXER_N;
            g.zr[s] = zrD;
        }
        zlzr_b<<<dim3(EXER_N, 3), 128>>>(g);
    }

    // ---- layers 2,3 (self-loop only), batched z=2, dual-store into ABCD+ABPCD --
    {
        GB g{};
        for (int i = 0; i < 2; i++) {
            g.A[i] = stu_table;
            g.B[i] = gat_W + (size_t)(2 + i) * DD * HD;
            g.C[i] = scr(i, SC_fS);
        }
        tgemm_b<<<dim3(HD / 128, gM_S, 2), 256>>>(g, DD, HD, 0, STU_N, HD, DD);
    }
    {
        GB g{};
        for (int i = 0; i < 2; i++) {
            int coff = (i == 0) ? 2 * DD : 3 * DD;
            g.A[i] = scr(i, SC_fS);
            g.B[i] = fc_W + (size_t)(2 + i) * HD * DD;
            g.C[i] = ABCD + coff;
            g.C2[i] = ABPCD + coff;
            g.bias[i] = bz + (size_t)(2 + i) * DD;
        }
        tgemm_b<<<dim3(DD / 128, gM_S, 2), 256>>>(g, HD, 4 * DD, 0, STU_N, DD, HD);
    }

    // ---- batched run_gat ----
    auto run_gat_batch = [&](int nz, const int* slot, const float* const* xS,
                             float* const* outb, float* const* outb2, int ldo) {
        {
            GB g{};
            for (int i = 0; i < nz; i++) {
                g.A[i] = xS[i];
                g.B[i] = gat_W + (size_t)pidx[slot[i]] * DD * HD;
                g.C[i] = scr(i, SC_fS);
            }
            tgemm_b<<<dim3(HD / 128, gM_S, nz), 256>>>(g, DD, HD, 0, STU_N, HD, DD);
        }
        {
            EEB g{};
            for (int i = 0; i < nz; i++) {
                g.f[i]  = scr(i, SC_fS);
                g.al[i] = attn_l + (size_t)pidx[slot[i]] * HD;
                g.ar[i] = attn_r + (size_t)pidx[slot[i]] * HD;
                g.el[i] = scr(i, SC_elS);
                g.er[i] = scr(i, SC_erS);
            }
            el_er_b<<<dim3(STU_N, nz), 128>>>(g);
        }
        {
            A1B g{};
            for (int i = 0; i < nz; i++) {
                int s = slot[i];
                g.adj[i] = adjP(s); g.cnt[i] = cntP(s);
                g.elE[i] = elE + (size_t)s * EXER_N * 3;
                g.elS[i] = scr(i, SC_elS);
                g.erS[i] = scr(i, SC_erS);
                g.fE[i]  = fE + (size_t)s * EXER_N * HD;
                g.fS[i]  = scr(i, SC_fS);
                g.rst[i] = scr(i, SC_rst);
            }
            attn1_b<<<dim3(STU_N, nz), 128>>>(g);
        }
        {
            GB g{};
            for (int i = 0; i < nz; i++) {
                g.A[i] = scr(i, SC_rst);
                g.B[i] = fc_W + (size_t)pidx[slot[i]] * HD * DD;
                g.C[i] = scr(i, SC_zS);
                g.bias[i] = bz + (size_t)pidx[slot[i]] * DD;
            }
            tgemm_b<<<dim3(DD / 128, gM_S, nz), 256>>>(g, HD, DD, 0, STU_N, DD, HD);
        }
        {
            ZZB g{};
            for (int i = 0; i < nz; i++) {
                g.z[i]  = scr(i, SC_zS);
                g.aW[i] = aW + (size_t)pidx[slot[i]] * 2 * DD;
                g.zl[i] = scr(i, SC_zlS);
                g.zr[i] = scr(i, SC_zrS);
            }
            zlzr_b<<<dim3(STU_N, nz), 128>>>(g);
        }
        {
            A2B g{};
            for (int i = 0; i < nz; i++) {
                int s = slot[i];
                g.adj[i] = adjP(s); g.cnt[i] = cntP(s);
                g.zlE[i] = zlE + (size_t)s * EXER_N;
                g.zlS[i] = scr(i, SC_zlS);
                g.zrS[i] = scr(i, SC_zrS);
                g.zE[i]  = zE + (size_t)s * EXER_N * DD;
                g.zS[i]  = scr(i, SC_zS);
                g.out[i]  = outb[i];
                g.out2[i] = outb2 ? outb2[i] : nullptr;
            }
            attn2_b<<<dim3(STU_N, nz), 128>>>(g, ldo);
        }
    };

    // ---- phase B: round-1 GAT (a, b, bp), batched z=3 ----
    {
        const int slot[3] = {0, 1, 2};
        const float* xS[3]  = {stu_table, stu_table, stu_table};
        float* outb[3]  = {ABCD, ABCD + DD, ABPCD + DD};
        float* outb2[3] = {ABPCD, nullptr, nullptr};
        run_gat_batch(3, slot, xS, outb, outb2, 4 * DD);
    }

    // ---- fuse1: K=512 GEMM + residual, batched z=2 ----
    {
        GB g{};
        g.A[0] = ABCD;  g.C[0] = stu1;  g.bias[0] = f1b; g.addm[0] = stu_table;
        g.A[1] = ABPCD; g.C[1] = stu1p; g.bias[1] = f1b; g.addm[1] = stu_table;
        g.B[0] = f1W; g.B[1] = f1W;
        tgemm_b<<<dim3(DD / 128, gM_S, 2), 256>>>(g, 4 * DD, DD, DD, STU_N, DD, 4 * DD);
    }

    // ---- phase D: expr2 on both branches, batched z=4 ----
    {
        const int slot[4] = {0, 1, 0, 1};
        const float* xS[4] = {stu1, stu1, stu1p, stu1p};
        float* outb[4] = {XYX, XYX + DD, XYP, XYP + DD};
        run_gat_batch(4, slot, xS, outb, nullptr, 2 * DD);
    }

    // ---- fusion2: K=256 + residual, batched z=2 ----
    {
        GB g{};
        g.A[0] = XYX; g.C[0] = stu2;  g.bias[0] = f2b; g.addm[0] = stu1;
        g.A[1] = XYP; g.C[1] = stu2p; g.bias[1] = f2b; g.addm[1] = stu1p;
        g.B[0] = f2W; g.B[1] = f2W;
        tgemm_b<<<dim3(DD / 128, gM_S, 2), 256>>>(g, 2 * DD, DD, DD, STU_N, DD, 2 * DD);
    }

    // ---- outputs ----
    const int NOUT = STU_N * DD;
    if (out_size >= NOUT)
        copy_f<<<(NOUT + 255) / 256, 256>>>(stu2, d_out, NOUT);

    float* lossdst = lossD;
    if (out_size == 1) lossdst = d_out;
    else if (out_size > NOUT) lossdst = d_out + (out_size - 1);

    {
        NRB g{};
        g.emb[0] = stu2;  g.out[0] = nb;
        g.emb[1] = stu2p; g.out[1] = nbp;
        norm_rows_b<<<dim3(BATCH, 2), 128>>>(g, stu_id);
    }
    colsum<<<1, 128>>>(nbp, Sv);
    loss_kernel<<<1, 256>>>(nb, nbp, Sv, lossdst);
}

// round 6
// speedup vs baseline: 1.6012x; 1.0637x over previous
#include <cuda_runtime.h>
#include <math.h>
#include <stdint.h>

#define EXER_N 10000
#define STU_N  20000
#define DD     128
#define HH     3
#define HD     384
#define CAP    96
#define BATCH  2048

#define SZF(x) ((size_t)(x))

// ---------------- scratch arena ---------------------------------------------
static constexpr size_t O_fE    = 0;                                    // 3*EXER_N*HD
static constexpr size_t O_elE   = O_fE    + SZF(3)*EXER_N*HD;
static constexpr size_t O_erD   = O_elE   + SZF(3)*EXER_N*3;            // dump
static constexpr size_t O_zE    = O_erD   + SZF(EXER_N)*3;
static constexpr size_t O_zlE   = O_zE    + SZF(3)*EXER_N*DD;
static constexpr size_t O_zrD   = O_zlE   + SZF(3)*EXER_N;              // dump
static constexpr size_t O_bz    = O_zrD   + SZF(EXER_N);
static constexpr size_t O_ABCD  = O_bz    + SZF(5)*DD;                  // 20000x512
static constexpr size_t O_ABPCD = O_ABCD  + SZF(STU_N)*4*DD;            // 20000x512
static constexpr size_t O_stu1  = O_ABPCD + SZF(STU_N)*4*DD;
static constexpr size_t O_stu1p = O_stu1  + SZF(STU_N)*DD;
static constexpr size_t O_XYX   = O_stu1p + SZF(STU_N)*DD;              // 20000x256
static constexpr size_t O_XYP   = O_XYX   + SZF(STU_N)*2*DD;            // 20000x256
static constexpr size_t O_stu2  = O_XYP   + SZF(STU_N)*2*DD;
static constexpr size_t O_stu2p = O_stu2  + SZF(STU_N)*DD;
static constexpr size_t O_nb    = O_stu2p + SZF(STU_N)*DD;
static constexpr size_t O_nbp   = O_nb    + SZF(BATCH)*DD;
static constexpr size_t O_S     = O_nbp   + SZF(BATCH)*DD;
static constexpr size_t O_lossd = O_S     + DD;
static constexpr size_t O_SCR   = O_lossd + 16;
// per-instance scratch set (x4)
static constexpr size_t SC_fS   = 0;                                    // STU_N*HD
static constexpr size_t SC_elS  = SC_fS  + SZF(STU_N)*HD;
static constexpr size_t SC_erS  = SC_elS + SZF(STU_N)*3;
static constexpr size_t SC_rst  = SC_erS + SZF(STU_N)*3;
static constexpr size_t SC_zS   = SC_rst + SZF(STU_N)*HD;
static constexpr size_t SC_zlS  = SC_zS  + SZF(STU_N)*DD;
static constexpr size_t SC_zrS  = SC_zlS + SZF(STU_N);
static constexpr size_t SC_TOT  = SC_zrS + SZF(STU_N);
static constexpr size_t F_TOT   = O_SCR + 4*SC_TOT;

static constexpr size_t OI_adj  = 0;                                    // 3*STU_N*CAP
static constexpr size_t OI_cnt  = SZF(3)*STU_N*CAP;
static constexpr size_t I_TOT   = OI_cnt + SZF(3)*STU_N;

__device__ __align__(256) float g_farena[F_TOT];
__device__ __align__(256) int   g_iarena[I_TOT];

// ---------------- batched pointer structs ------------------------------------
struct GB {
    const float* A[4];
    const float* B[4];
    float*       C[4];
    float*       C2[4];
    const float* bias[4];
    const float* addm[4];
};
struct EEB {
    const float* f[4];
    const float* al[4];
    const float* ar[4];
    float*       el[4];
    float*       er[4];
};
struct ZZB {
    const float* z[4];
    const float* aW[4];
    float*       zl[4];
    float*       zr[4];
};
struct A1B {
    const int*   adj[4];
    const int*   cnt[4];
    const float* elE[4];
    const float* elS[4];
    const float* erS[4];
    const float* fE[4];
    const float* fS[4];
    float*       rst[4];
};
struct A2B {
    const int*   adj[4];
    const int*   cnt[4];
    const float* zlE[4];
    const float* zlS[4];
    const float* zrS[4];
    const float* zE[4];
    const float* zS[4];
    float*       out[4];
    float*       out2[4];
};
struct ADJB {
    const int* src[3];
    const int* dst[3];
    int        ecnt[3];
    int*       adj[3];
    int*       cnt[3];
};
struct NRB {
    const float* emb[2];
    float*       out[2];
};

// ---------------- TF32 tensor-core batched GEMM (v2: pipelined) --------------
// C = A[MxK](lda) @ B[KxN] (+bias)(+addm), fp32 accumulate, tf32 inputs.
// 128x128 block tile, BK=16, 256 threads = 8 warps (4m x 2n), warp tile 32x64.
// Double-buffered smem, register prefetch, ONE __syncthreads per K-tile.
// Requires: N % 128 == 0, K % 16 == 0. M arbitrary.

__device__ __forceinline__ uint32_t f2tf32(float x) {
    uint32_t u;
    asm("cvt.rna.tf32.f32 %0, %1;" : "=r"(u) : "f"(x));
    return u;
}
__device__ __forceinline__ void mma_tf32(float* c, uint32_t a0, uint32_t a1,
                                         uint32_t a2, uint32_t a3,
                                         uint32_t b0, uint32_t b1) {
    asm volatile(
        "mma.sync.aligned.m16n8k8.row.col.f32.tf32.tf32.f32 "
        "{%0,%1,%2,%3}, {%4,%5,%6,%7}, {%8,%9}, {%0,%1,%2,%3};"
        : "+f"(c[0]), "+f"(c[1]), "+f"(c[2]), "+f"(c[3])
        : "r"(a0), "r"(a1), "r"(a2), "r"(a3), "r"(b0), "r"(b1));
}

#define SPAD 136   // padded row stride; 136 mod 32 == 8 -> conflict-free frags

__global__ __launch_bounds__(256, 2)
void tgemm_b(GB g, int lda, int ldc, int ldadd, int M, int N, int K)
{
    const int z = blockIdx.z;
    const float* __restrict__ A    = g.A[z];
    const float* __restrict__ B    = g.B[z];
    float*       __restrict__ C    = g.C[z];
    float*                    C2   = g.C2[z];
    const float*              bias = g.bias[z];
    const float*              addm = g.addm[z];

    __shared__ uint32_t As[2][16][SPAD];
    __shared__ uint32_t Bs[2][16][SPAD];

    const int tid  = threadIdx.x;
    const int bm   = blockIdx.y * 128;
    const int bn   = blockIdx.x * 128;
    const int lane = tid & 31;
    const int gid  = lane >> 2;       // 0..7
    const int tg   = lane & 3;        // 0..3
    const int warp = tid >> 5;
    const int wm   = warp & 3;        // m offset wm*32
    const int wn   = warp >> 2;       // n offset wn*64

    float acc[2][8][4];
#pragma unroll
    for (int mt = 0; mt < 2; mt++)
#pragma unroll
        for (int nt = 0; nt < 8; nt++)
#pragma unroll
            for (int c = 0; c < 4; c++) acc[mt][nt][c] = 0.f;

    // staging indices
    const int am  = tid >> 1;            // 0..127 (A row within tile)
    const int ak0 = (tid & 1) * 4;       // 0 or 4
    const int brr = tid >> 5;            // 0..7 (B row)
    const int bcc = (tid & 31) * 4;      // 0..124

    const bool arow_ok = (bm + am < M);
    float4 av0, av1, bv0, bv1;

    auto ldtile = [&](int k0) {
        av0 = arow_ok ? *(const float4*)(A + (size_t)(bm + am) * lda + k0 + ak0)
                      : make_float4(0.f, 0.f, 0.f, 0.f);
        av1 = arow_ok ? *(const float4*)(A + (size_t)(bm + am) * lda + k0 + 8 + ak0)
                      : make_float4(0.f, 0.f, 0.f, 0.f);
        bv0 = *(const float4*)(B + (size_t)(k0 + brr) * N + bn + bcc);
        bv1 = *(const float4*)(B + (size_t)(k0 + 8 + brr) * N + bn + bcc);
    };
    auto sttile = [&](int p) {
        As[p][ak0 + 0][am] = f2tf32(av0.x);
        As[p][ak0 + 1][am] = f2tf32(av0.y);
        As[p][ak0 + 2][am] = f2tf32(av0.z);
        As[p][ak0 + 3][am] = f2tf32(av0.w);
        As[p][8 + ak0 + 0][am] = f2tf32(av1.x);
        As[p][8 + ak0 + 1][am] = f2tf32(av1.y);
        As[p][8 + ak0 + 2][am] = f2tf32(av1.z);
        As[p][8 + ak0 + 3][am] = f2tf32(av1.w);
        uint4 t0 = make_uint4(f2tf32(bv0.x), f2tf32(bv0.y), f2tf32(bv0.z), f2tf32(bv0.w));
        uint4 t1 = make_uint4(f2tf32(bv1.x), f2tf32(bv1.y), f2tf32(bv1.z), f2tf32(bv1.w));
        *(uint4*)(&Bs[p][brr][bcc]) = t0;
        *(uint4*)(&Bs[p][8 + brr][bcc]) = t1;
    };

    ldtile(0);
    sttile(0);

    const int nt_tiles = K / 16;
    for (int kt = 0; kt < nt_tiles; kt++) {
        const int p = kt & 1;
        const bool more = (kt + 1 < nt_tiles);
        if (more) ldtile((kt + 1) * 16);   // prefetch next tile into regs
        __syncthreads();                   // buf p visible; buf p^1 free

#pragma unroll
        for (int ks = 0; ks < 2; ks++) {
            const int kk = ks * 8;
            uint32_t bf[8][2];
#pragma unroll
            for (int nt = 0; nt < 8; nt++) {
                const int n0 = wn * 64 + nt * 8 + gid;
                bf[nt][0] = Bs[p][kk + tg][n0];
                bf[nt][1] = Bs[p][kk + tg + 4][n0];
            }
#pragma unroll
            for (int mt = 0; mt < 2; mt++) {
                const int m0 = wm * 32 + mt * 16;
                uint32_t a0 = As[p][kk + tg][m0 + gid];
                uint32_t a1 = As[p][kk + tg][m0 + gid + 8];
                uint32_t a2 = As[p][kk + tg + 4][m0 + gid];
                uint32_t a3 = As[p][kk + tg + 4][m0 + gid + 8];
#pragma unroll
                for (int nt = 0; nt < 8; nt++)
                    mma_tf32(acc[mt][nt], a0, a1, a2, a3, bf[nt][0], bf[nt][1]);
            }
        }
        if (more) sttile(p ^ 1);           // store prefetched tile (overlapped)
    }

    // epilogue
#pragma unroll
    for (int mt = 0; mt < 2; mt++) {
        const int r0 = bm + wm * 32 + mt * 16 + gid;
        const int r1 = r0 + 8;
#pragma unroll
        for (int nt = 0; nt < 8; nt++) {
            const int n = bn + wn * 64 + nt * 8 + tg * 2;
            float2 v0 = make_float2(acc[mt][nt][0], acc[mt][nt][1]);
            float2 v1 = make_float2(acc[mt][nt][2], acc[mt][nt][3]);
            if (bias) {
                float b0 = bias[n], b1 = bias[n + 1];
                v0.x += b0; v0.y += b1;
                v1.x += b0; v1.y += b1;
            }
            if (r0 < M) {
                float2 o = v0;
                if (addm) {
                    const float2 ad = *(const float2*)(addm + (size_t)r0 * ldadd + n);
                    o.x += ad.x; o.y += ad.y;
                }
                *(float2*)(C + (size_t)r0 * ldc + n) = o;
                if (C2) *(float2*)(C2 + (size_t)r0 * ldc + n) = o;
            }
            if (r1 < M) {
                float2 o = v1;
                if (addm) {
                    const float2 ad = *(const float2*)(addm + (size_t)r1 * ldadd + n);
                    o.x += ad.x; o.y += ad.y;
                }
                *(float2*)(C + (size_t)r1 * ldc + n) = o;
                if (C2) *(float2*)(C2 + (size_t)r1 * ldc + n) = o;
            }
        }
    }
}

// ---------------- small batched kernels ---------------------------------------
__global__ void zero_int(int* p, int n) {
    int i = blockIdx.x * blockDim.x + threadIdx.x;
    if (i < n) p[i] = 0;
}
__global__ void copy_f(const float* __restrict__ s, float* __restrict__ d, int n) {
    int i = blockIdx.x * blockDim.x + threadIdx.x;
    if (i < n) d[i] = s[i];
}
__global__ void build_adj_b(ADJB g) {
    int z = blockIdx.y;
    int i = blockIdx.x * blockDim.x + threadIdx.x;
    if (i >= g.ecnt[z]) return;
    int d = g.dst[z][i];
    if (d < EXER_N) return;
    int dl = d - EXER_N;
    int slot = atomicAdd(&g.cnt[z][dl], 1);
    if (slot < CAP) g.adj[z][(size_t)dl * CAP + slot] = g.src[z][i];
}
__global__ void bz_kernel(const float* __restrict__ gb, const float* __restrict__ fcW,
                          const float* __restrict__ fcb, float* __restrict__ bz) {
    int p = blockIdx.x, n = threadIdx.x;
    const float* g = gb + (size_t)p * HD;
    const float* W = fcW + (size_t)p * HD * DD;
    float s = fcb[(size_t)p * DD + n];
    for (int k = 0; k < HD; k++) s += g[k] * W[(size_t)k * DD + n];
    bz[(size_t)p * DD + n] = s;
}
__global__ void el_er_b(EEB g) {
    int z = blockIdx.y;
    int n = blockIdx.x, t = threadIdx.x;
    const float* fr = g.f[z] + (size_t)n * HD;
    const float* al = g.al[z];
    const float* ar = g.ar[z];
    float pel[3], per[3];
#pragma unroll
    for (int h = 0; h < 3; h++) {
        float v = fr[h * DD + t];
        pel[h] = v * al[h * DD + t];
        per[h] = v * ar[h * DD + t];
    }
#pragma unroll
    for (int off = 16; off; off >>= 1) {
#pragma unroll
        for (int h = 0; h < 3; h++) {
            pel[h] += __shfl_xor_sync(0xffffffffu, pel[h], off);
            per[h] += __shfl_xor_sync(0xffffffffu, per[h], off);
        }
    }
    __shared__ float red[4][6];
    int w = t >> 5;
    if ((t & 31) == 0) {
#pragma unroll
        for (int h = 0; h < 3; h++) { red[w][h] = pel[h]; red[w][3 + h] = per[h]; }
    }
    __syncthreads();
    if (t < 6) {
        float v = red[0][t] + red[1][t] + red[2][t] + red[3][t];
        if (t < 3) g.el[z][(size_t)n * 3 + t] = v;
        else       g.er[z][(size_t)n * 3 + (t - 3)] = v;
    }
}
__global__ void zlzr_b(ZZB g) {
    int z = blockIdx.y;
    int n = blockIdx.x, t = threadIdx.x;
    float v = g.z[z][(size_t)n * DD + t];
    float a = v * g.aW[z][t];
    float b = v * g.aW[z][DD + t];
#pragma unroll
    for (int off = 16; off; off >>= 1) {
        a += __shfl_xor_sync(0xffffffffu, a, off);
        b += __shfl_xor_sync(0xffffffffu, b, off);
    }
    __shared__ float red[4][2];
    int w = t >> 5;
    if ((t & 31) == 0) { red[w][0] = a; red[w][1] = b; }
    __syncthreads();
    if (t < 2) {
        float v2 = red[0][t] + red[1][t] + red[2][t] + red[3][t];
        if (t == 0) g.zl[z][n] = v2; else g.zr[z][n] = v2;
    }
}
__global__ void attn1_b(A1B g) {
    int z = blockIdx.y;
    int dl = blockIdx.x, t = threadIdx.x;
    int deg = g.cnt[z][dl]; if (deg > CAP) deg = CAP;
    const float* elE = g.elE[z];
    const float* elS = g.elS[z];
    const float* fE  = g.fE[z];
    const float* fS  = g.fS[z];
    __shared__ int   ssrc[CAP];
    __shared__ float se[CAP * 3];
    __shared__ float sm[3], ssum[3];
    float er0 = g.erS[z][(size_t)dl * 3 + 0];
    float er1 = g.erS[z][(size_t)dl * 3 + 1];
    float er2 = g.erS[z][(size_t)dl * 3 + 2];
    if (t < deg) {
        int s = g.adj[z][(size_t)dl * CAP + t];
        ssrc[t] = s;
        const float* el = (s < EXER_N) ? (elE + (size_t)s * 3) : (elS + (size_t)(s - EXER_N) * 3);
        float e0 = el[0] + er0, e1 = el[1] + er1, e2 = el[2] + er2;
        se[t * 3 + 0] = e0 > 0.f ? e0 : 0.2f * e0;
        se[t * 3 + 1] = e1 > 0.f ? e1 : 0.2f * e1;
        se[t * 3 + 2] = e2 > 0.f ? e2 : 0.2f * e2;
    }
    __syncthreads();
    int w = t >> 5, lane = t & 31;
    if (w < 3) {
        float m = -3.0e38f;
        for (int j = lane; j < deg; j += 32) m = fmaxf(m, se[j * 3 + w]);
#pragma unroll
        for (int off = 16; off; off >>= 1) m = fmaxf(m, __shfl_xor_sync(0xffffffffu, m, off));
        float s = 0.f;
        for (int j = lane; j < deg; j += 32) s += expf(se[j * 3 + w] - m);
#pragma unroll
        for (int off = 16; off; off >>= 1) s += __shfl_xor_sync(0xffffffffu, s, off);
        if (lane == 0) { sm[w] = m; ssum[w] = s; }
    }
    __syncthreads();
    if (t < deg) {
#pragma unroll
        for (int h = 0; h < 3; h++)
            se[t * 3 + h] = expf(se[t * 3 + h] - sm[h]) / ssum[h];
    }
    __syncthreads();
    float a0 = 0.f, a1 = 0.f, a2 = 0.f;
    for (int j = 0; j < deg; j++) {
        int s = ssrc[j];
        const float* fr = (s < EXER_N) ? (fE + (size_t)s * HD) : (fS + (size_t)(s - EXER_N) * HD);
        float w0 = se[j * 3 + 0], w1 = se[j * 3 + 1], w2 = se[j * 3 + 2];
        a0 += w0 * fr[t];
        a1 += w1 * fr[DD + t];
        a2 += w2 * fr[2 * DD + t];
    }
    size_t o = (size_t)dl * HD;
    float* rst = g.rst[z];
    rst[o + t] = a0; rst[o + DD + t] = a1; rst[o + 2 * DD + t] = a2;
}
__global__ void attn2_b(A2B g, int ldo) {
    int z = blockIdx.y;
    int dl = blockIdx.x, t = threadIdx.x;
    int deg = g.cnt[z][dl]; if (deg > CAP) deg = CAP;
    const float* zlE = g.zlE[z];
    const float* zlS = g.zlS[z];
    const float* zE  = g.zE[z];
    const float* zS  = g.zS[z];
    __shared__ int   ssrc[CAP];
    __shared__ float se[CAP];
    __shared__ float smx, ssm;
    float zr = g.zrS[z][dl];
    if (t < deg) {
        int s = g.adj[z][(size_t)dl * CAP + t];
        ssrc[t] = s;
        float zl = (s < EXER_N) ? zlE[s] : zlS[s - EXER_N];
        se[t] = zl + zr;
    }
    __syncthreads();
    if (t < 32) {
        float m = -3.0e38f;
        for (int j = t; j < deg; j += 32) m = fmaxf(m, se[j]);
#pragma unroll
        for (int off = 16; off; off >>= 1) m = fmaxf(m, __shfl_xor_sync(0xffffffffu, m, off));
        float s = 0.f;
        for (int j = t; j < deg; j += 32) s += expf(se[j] - m);
#pragma unroll
        for (int off = 16; off; off >>= 1) s += __shfl_xor_sync(0xffffffffu, s, off);
        if (t == 0) { smx = m; ssm = s; }
    }
    __syncthreads();
    if (t < deg) se[t] = expf(se[t] - smx) / ssm;
    __syncthreads();
    float acc = 0.f;
    for (int j = 0; j < deg; j++) {
        int s = ssrc[j];
        const float* zrow = (s < EXER_N) ? (zE + (size_t)s * DD) : (zS + (size_t)(s - EXER_N) * DD);
        acc += se[j] * zrow[t];
    }
    g.out[z][(size_t)dl * ldo + t] = acc;
    if (g.out2[z]) g.out2[z][(size_t)dl * ldo + t] = acc;
}

// SSL ------------------------------------------------------------------------
__global__ void norm_rows_b(NRB g, const int* __restrict__ ids) {
    int z = blockIdx.y;
    int i = blockIdx.x, t = threadIdx.x;
    int r = ids[i];
    float v = g.emb[z][(size_t)r * DD + t];
    float sq = v * v;
#pragma unroll
    for (int off = 16; off; off >>= 1) sq += __shfl_xor_sync(0xffffffffu, sq, off);
    __shared__ float w4[4];
    if ((t & 31) == 0) w4[t >> 5] = sq;
    __syncthreads();
    float tot = w4[0] + w4[1] + w4[2] + w4[3];
    float nrm = sqrtf(tot);
    g.out[z][(size_t)i * DD + t] = v / fmaxf(nrm, 1e-12f);
}
__global__ void colsum(const float* __restrict__ nbp, float* __restrict__ S) {
    int t = threadIdx.x;
    float s = 0.f;
    for (int i = 0; i < BATCH; i++) s += nbp[(size_t)i * DD + t];
    S[t] = s;
}
__global__ void loss_kernel(const float* __restrict__ nb, const float* __restrict__ nbp,
                            const float* __restrict__ S, float* __restrict__ out) {
    int t = threadIdx.x;
    float lsum = 0.f;
    for (int i = t; i < BATCH; i += 256) {
        const float* x = nb  + (size_t)i * DD;
        const float* y = nbp + (size_t)i * DD;
        float dg = 0.f, rs = 0.f;
        for (int d = 0; d < DD; d++) {
            float xv = x[d];
            dg += xv * y[d];
            rs += xv * S[d];
        }
        float divided = expf(dg * 5.0f) / (rs * 5.0f + 1e-8f);
        lsum += -logf(fmaxf(divided, 1e-8f));
    }
    __shared__ float red[256];
    red[t] = lsum;
    __syncthreads();
    for (int s = 128; s; s >>= 1) { if (t < s) red[t] += red[t + s]; __syncthreads(); }
    if (t == 0) out[0] = red[0];
}

// ---------------- host orchestration ------------------------------------------
extern "C" void kernel_launch(void* const* d_in, const int* in_sizes, int n_in,
                              void* d_out_, int out_size)
{
    const float* stu_table  = (const float*)d_in[0];
    const float* exer_table = (const float*)d_in[1];
    const float* gat_W  = (const float*)d_in[2];
    const float* attn_l = (const float*)d_in[3];
    const float* attn_r = (const float*)d_in[4];
    const float* gat_b  = (const float*)d_in[5];
    const float* fc_W   = (const float*)d_in[6];
    const float* fc_b   = (const float*)d_in[7];
    const float* aW     = (const float*)d_in[8];
    const float* f1W    = (const float*)d_in[9];
    const float* f1b    = (const float*)d_in[10];
    const float* f2W    = (const float*)d_in[11];
    const float* f2b    = (const float*)d_in[12];
    const int* e_src[3] = {(const int*)d_in[13], (const int*)d_in[15], (const int*)d_in[21]};
    const int* e_dst[3] = {(const int*)d_in[14], (const int*)d_in[16], (const int*)d_in[22]};
    int e_n[3] = {in_sizes[13], in_sizes[15], in_sizes[21]};
    const int* stu_id = (const int*)d_in[23];
    float* d_out = (float*)d_out_;
    (void)n_in;

    float* FA = nullptr; int* IA = nullptr;
    cudaGetSymbolAddress((void**)&FA, g_farena);
    cudaGetSymbolAddress((void**)&IA, g_iarena);

    float* fE    = FA + O_fE;
    float* elE   = FA + O_elE;
    float* erD   = FA + O_erD;
    float* zE    = FA + O_zE;
    float* zlE   = FA + O_zlE;
    float* zrD   = FA + O_zrD;
    float* bz    = FA + O_bz;
    float* ABCD  = FA + O_ABCD;
    float* ABPCD = FA + O_ABPCD;
    float* stu1  = FA + O_stu1;
    float* stu1p = FA + O_stu1p;
    float* XYX   = FA + O_XYX;
    float* XYP   = FA + O_XYP;
    float* stu2  = FA + O_stu2;
    float* stu2p = FA + O_stu2p;
    float* nb    = FA + O_nb;
    float* nbp   = FA + O_nbp;
    float* Sv    = FA + O_S;
    float* lossD = FA + O_lossd;

    const int pidx[3] = {0, 1, 4};
    const int gM_E = (EXER_N + 127) / 128;
    const int gM_S = (STU_N + 127) / 128;

    auto scr  = [&](int sc, size_t off) { return FA + O_SCR + (size_t)sc * SC_TOT + off; };
    auto adjP = [&](int s) { return IA + OI_adj + (size_t)s * STU_N * CAP; };
    auto cntP = [&](int s) { return IA + OI_cnt + (size_t)s * STU_N; };

    // ---- bias precompute + adjacency ----
    bz_kernel<<<5, 128>>>(gat_b, fc_W, fc_b, bz);
    zero_int<<<(3 * STU_N + 255) / 256, 256>>>(IA + OI_cnt, 3 * STU_N);
    {
        ADJB g{};
        int max_e = 0;
        for (int s = 0; s < 3; s++) {
            g.src[s] = e_src[s]; g.dst[s] = e_dst[s]; g.ecnt[s] = e_n[s];
            g.adj[s] = adjP(s);  g.cnt[s] = cntP(s);
            if (e_n[s] > max_e) max_e = e_n[s];
        }
        build_adj_b<<<dim3((max_e + 255) / 256, 3), 256>>>(g);
    }

    // ---- phase A: exer-side invariants (batched z=3) ----
    {
        GB g{};
        for (int s = 0; s < 3; s++) {
            g.A[s] = exer_table;
            g.B[s] = gat_W + (size_t)pidx[s] * DD * HD;
            g.C[s] = fE + (size_t)s * EXER_N * HD;
        }
        tgemm_b<<<dim3(HD / 128, gM_E, 3), 256>>>(g, DD, HD, 0, EXER_N, HD, DD);
    }
    {
        EEB g{};
        for (int s = 0; s < 3; s++) {
            g.f[s]  = fE + (size_t)s * EXER_N * HD;
            g.al[s] = attn_l + (size_t)pidx[s] * HD;
            g.ar[s] = attn_r + (size_t)pidx[s] * HD;
            g.el[s] = elE + (size_t)s * EXER_N * 3;
            g.er[s] = erD;
        }
        el_er_b<<<dim3(EXER_N, 3), 128>>>(g);
    }
    {
        GB g{};
        for (int s = 0; s < 3; s++) {
            g.A[s] = fE + (size_t)s * EXER_N * HD;
            g.B[s] = fc_W + (size_t)pidx[s] * HD * DD;
            g.C[s] = zE + (size_t)s * EXER_N * DD;
            g.bias[s] = bz + (size_t)pidx[s] * DD;
        }
        tgemm_b<<<dim3(DD / 128, gM_E, 3), 256>>>(g, HD, DD, 0, EXER_N, DD, HD);
    }
    {
        ZZB g{};
        for (int s = 0; s < 3; s++) {
            g.z[s]  = zE + (size_t)s * EXER_N * DD;
            g.aW[s] = aW + (size_t)pidx[s] * 2 * DD;
            g.zl[s] = zlE + (size_t)s * EXER_N;
            g.zr[s] = zrD;
        }
        zlzr_b<<<dim3(EXER_N, 3), 128>>>(g);
    }

    // ---- layers 2,3 (self-loop only), batched z=2, dual-store into ABCD+ABPCD --
    {
        GB g{};
        for (int i = 0; i < 2; i++) {
            g.A[i] = stu_table;
            g.B[i] = gat_W + (size_t)(2 + i) * DD * HD;
            g.C[i] = scr(i, SC_fS);
        }
        tgemm_b<<<dim3(HD / 128, gM_S, 2), 256>>>(g, DD, HD, 0, STU_N, HD, DD);
    }
    {
        GB g{};
        for (int i = 0; i < 2; i++) {
            int coff = (i == 0) ? 2 * DD : 3 * DD;
            g.A[i] = scr(i, SC_fS);
            g.B[i] = fc_W + (size_t)(2 + i) * HD * DD;
            g.C[i] = ABCD + coff;
            g.C2[i] = ABPCD + coff;
            g.bias[i] = bz + (size_t)(2 + i) * DD;
        }
        tgemm_b<<<dim3(DD / 128, gM_S, 2), 256>>>(g, HD, 4 * DD, 0, STU_N, DD, HD);
    }

    // ---- batched run_gat ----
    auto run_gat_batch = [&](int nz, const int* slot, const float* const* xS,
                             float* const* outb, float* const* outb2, int ldo) {
        {
            GB g{};
            for (int i = 0; i < nz; i++) {
                g.A[i] = xS[i];
                g.B[i] = gat_W + (size_t)pidx[slot[i]] * DD * HD;
                g.C[i] = scr(i, SC_fS);
            }
            tgemm_b<<<dim3(HD / 128, gM_S, nz), 256>>>(g, DD, HD, 0, STU_N, HD, DD);
        }
        {
            EEB g{};
            for (int i = 0; i < nz; i++) {
                g.f[i]  = scr(i, SC_fS);
                g.al[i] = attn_l + (size_t)pidx[slot[i]] * HD;
                g.ar[i] = attn_r + (size_t)pidx[slot[i]] * HD;
                g.el[i] = scr(i, SC_elS);
                g.er[i] = scr(i, SC_erS);
            }
            el_er_b<<<dim3(STU_N, nz), 128>>>(g);
        }
        {
            A1B g{};
            for (int i = 0; i < nz; i++) {
                int s = slot[i];
                g.adj[i] = adjP(s); g.cnt[i] = cntP(s);
                g.elE[i] = elE + (size_t)s * EXER_N * 3;
                g.elS[i] = scr(i, SC_elS);
                g.erS[i] = scr(i, SC_erS);
                g.fE[i]  = fE + (size_t)s * EXER_N * HD;
                g.fS[i]  = scr(i, SC_fS);
                g.rst[i] = scr(i, SC_rst);
            }
            attn1_b<<<dim3(STU_N, nz), 128>>>(g);
        }
        {
            GB g{};
            for (int i = 0; i < nz; i++) {
                g.A[i] = scr(i, SC_rst);
                g.B[i] = fc_W + (size_t)pidx[slot[i]] * HD * DD;
                g.C[i] = scr(i, SC_zS);
                g.bias[i] = bz + (size_t)pidx[slot[i]] * DD;
            }
            tgemm_b<<<dim3(DD / 128, gM_S, nz), 256>>>(g, HD, DD, 0, STU_N, DD, HD);
        }
        {
            ZZB g{};
            for (int i = 0; i < nz; i++) {
                g.z[i]  = scr(i, SC_zS);
                g.aW[i] = aW + (size_t)pidx[slot[i]] * 2 * DD;
                g.zl[i] = scr(i, SC_zlS);
                g.zr[i] = scr(i, SC_zrS);
            }
            zlzr_b<<<dim3(STU_N, nz), 128>>>(g);
        }
        {
            A2B g{};
            for (int i = 0; i < nz; i++) {
                int s = slot[i];
                g.adj[i] = adjP(s); g.cnt[i] = cntP(s);
                g.zlE[i] = zlE + (size_t)s * EXER_N;
                g.zlS[i] = scr(i, SC_zlS);
                g.zrS[i] = scr(i, SC_zrS);
                g.zE[i]  = zE + (size_t)s * EXER_N * DD;
                g.zS[i]  = scr(i, SC_zS);
                g.out[i]  = outb[i];
                g.out2[i] = outb2 ? outb2[i] : nullptr;
            }
            attn2_b<<<dim3(STU_N, nz), 128>>>(g, ldo);
        }
    };

    // ---- phase B: round-1 GAT (a, b, bp), batched z=3 ----
    {
        const int slot[3] = {0, 1, 2};
        const float* xS[3]  = {stu_table, stu_table, stu_table};
        float* outb[3]  = {ABCD, ABCD + DD, ABPCD + DD};
        float* outb2[3] = {ABPCD, nullptr, nullptr};
        run_gat_batch(3, slot, xS, outb, outb2, 4 * DD);
    }

    // ---- fuse1: K=512 GEMM + residual, batched z=2 ----
    {
        GB g{};
        g.A[0] = ABCD;  g.C[0] = stu1;  g.bias[0] = f1b; g.addm[0] = stu_table;
        g.A[1] = ABPCD; g.C[1] = stu1p; g.bias[1] = f1b; g.addm[1] = stu_table;
        g.B[0] = f1W; g.B[1] = f1W;
        tgemm_b<<<dim3(DD / 128, gM_S, 2), 256>>>(g, 4 * DD, DD, DD, STU_N, DD, 4 * DD);
    }

    // ---- phase D: expr2 on both branches, batched z=4 ----
    {
        const int slot[4] = {0, 1, 0, 1};
        const float* xS[4] = {stu1, stu1, stu1p, stu1p};
        float* outb[4] = {XYX, XYX + DD, XYP, XYP + DD};
        run_gat_batch(4, slot, xS, outb, nullptr, 2 * DD);
    }

    // ---- fusion2: K=256 + residual, batched z=2; stu2 dual-stored to d_out ----
    const int NOUT = STU_N * DD;
    {
        GB g{};
        g.A[0] = XYX; g.C[0] = stu2;  g.bias[0] = f2b; g.addm[0] = stu1;
        g.A[1] = XYP; g.C[1] = stu2p; g.bias[1] = f2b; g.addm[1] = stu1p;
        g.B[0] = f2W; g.B[1] = f2W;
        if (out_size >= NOUT) g.C2[0] = d_out;   // fused output copy
        tgemm_b<<<dim3(DD / 128, gM_S, 2), 256>>>(g, 2 * DD, DD, DD, STU_N, DD, 2 * DD);
    }

    float* lossdst = lossD;
    if (out_size == 1) lossdst = d_out;
    else if (out_size > NOUT) lossdst = d_out + (out_size - 1);

    {
        NRB g{};
        g.emb[0] = stu2;  g.out[0] = nb;
        g.emb[1] = stu2p; g.out[1] = nbp;
        norm_rows_b<<<dim3(BATCH, 2), 128>>>(g, stu_id);
    }
    colsum<<<1, 128>>>(nbp, Sv);
    loss_kernel<<<1, 256>>>(nb, nbp, Sv, lossdst);
}

// round 7
// speedup vs baseline: 1.6907x; 1.0559x over previous
#include <cuda_runtime.h>
#include <math.h>
#include <stdint.h>

#define EXER_N 10000
#define STU_N  20000
#define DD     128
#define HH     3
#define HD     384
#define CAP    96
#define BATCH  2048

#define SZF(x) ((size_t)(x))

// ---------------- scratch arena ---------------------------------------------
static constexpr size_t O_fE    = 0;                                    // 3*EXER_N*HD
static constexpr size_t O_elE   = O_fE    + SZF(3)*EXER_N*HD;
static constexpr size_t O_erD   = O_elE   + SZF(3)*EXER_N*3;            // dump
static constexpr size_t O_zE    = O_erD   + SZF(EXER_N)*3;
static constexpr size_t O_zlE   = O_zE    + SZF(3)*EXER_N*DD;
static constexpr size_t O_zrD   = O_zlE   + SZF(3)*EXER_N;              // dump
static constexpr size_t O_bz    = O_zrD   + SZF(EXER_N);
static constexpr size_t O_ABCD  = O_bz    + SZF(5)*DD;                  // 20000x512
static constexpr size_t O_ABPCD = O_ABCD  + SZF(STU_N)*4*DD;            // 20000x512
static constexpr size_t O_stu1  = O_ABPCD + SZF(STU_N)*4*DD;
static constexpr size_t O_stu1p = O_stu1  + SZF(STU_N)*DD;
static constexpr size_t O_XYX   = O_stu1p + SZF(STU_N)*DD;              // 20000x256
static constexpr size_t O_XYP   = O_XYX   + SZF(STU_N)*2*DD;            // 20000x256
static constexpr size_t O_stu2  = O_XYP   + SZF(STU_N)*2*DD;
static constexpr size_t O_stu2p = O_stu2  + SZF(STU_N)*DD;
static constexpr size_t O_nb    = O_stu2p + SZF(STU_N)*DD;
static constexpr size_t O_nbp   = O_nb    + SZF(BATCH)*DD;
static constexpr size_t O_S     = O_nbp   + SZF(BATCH)*DD;
static constexpr size_t O_lossd = O_S     + DD;
static constexpr size_t O_SCR   = O_lossd + 16;
// per-instance scratch set (x4)
static constexpr size_t SC_fS   = 0;                                    // STU_N*HD
static constexpr size_t SC_elS  = SC_fS  + SZF(STU_N)*HD;
static constexpr size_t SC_erS  = SC_elS + SZF(STU_N)*3 + 2;            // keep 16B align
static constexpr size_t SC_rst  = SC_erS + SZF(STU_N)*3 + 2;
static constexpr size_t SC_zS   = SC_rst + SZF(STU_N)*HD;
static constexpr size_t SC_zlS  = SC_zS  + SZF(STU_N)*DD;
static constexpr size_t SC_zrS  = SC_zlS + SZF(STU_N);
static constexpr size_t SC_TOT  = SC_zrS + SZF(STU_N);
static constexpr size_t F_TOT   = O_SCR + 4*SC_TOT;

static constexpr size_t OI_adj  = 0;                                    // 3*STU_N*CAP
static constexpr size_t OI_cnt  = SZF(3)*STU_N*CAP;
static constexpr size_t I_TOT   = OI_cnt + SZF(3)*STU_N;

__device__ __align__(256) float g_farena[F_TOT];
__device__ __align__(256) int   g_iarena[I_TOT];

// ---------------- batched pointer structs ------------------------------------
struct GB {
    const float* A[4];
    const float* B[4];
    float*       C[4];
    float*       C2[4];
    const float* bias[4];
    const float* addm[4];
};
struct EEB {
    const float* f[4];
    const float* al[4];
    const float* ar[4];
    float*       el[4];
    float*       er[4];
};
struct ZZB {
    const float* z[4];
    const float* aW[4];
    float*       zl[4];
    float*       zr[4];
};
struct A1B {                      // phase-B attn1 (single branch)
    const int*   adj[4];
    const int*   cnt[4];
    const float* elE[4];
    const float* elS[4];
    const float* erS[4];
    const float* fE[4];
    const float* fS[4];
    float*       rst[4];
};
struct A2B {                      // phase-B attn2 (single branch)
    const int*   adj[4];
    const int*   cnt[4];
    const float* zlE[4];
    const float* zlS[4];
    const float* zrS[4];
    const float* zE[4];
    const float* zS[4];
    float*       out[4];
    float*       out2[4];
};
struct A1M {                      // phase-D merged attn1 (two branches / slot)
    const int*   adj[2];
    const int*   cnt[2];
    const float* elE[2];
    const float* fE[2];
    const float* elSX[2];
    const float* erSX[2];
    const float* fSX[2];
    float*       rstX[2];
    const float* elSP[2];
    const float* erSP[2];
    const float* fSP[2];
    float*       rstP[2];
};
struct A2M {                      // phase-D merged attn2
    const int*   adj[2];
    const int*   cnt[2];
    const float* zlE[2];
    const float* zE[2];
    const float* zlSX[2];
    const float* zrSX[2];
    const float* zSX[2];
    float*       outX[2];
    const float* zlSP[2];
    const float* zrSP[2];
    const float* zSP[2];
    float*       outP[2];
};
struct ADJB {
    const int* src[3];
    const int* dst[3];
    int        ecnt[3];
    int*       adj[3];
    int*       cnt[3];
};
struct NRB {
    const float* emb[2];
    float*       out[2];
};

// ---------------- TF32 tensor-core batched GEMM (pipelined) ------------------
__device__ __forceinline__ uint32_t f2tf32(float x) {
    uint32_t u;
    asm("cvt.rna.tf32.f32 %0, %1;" : "=r"(u) : "f"(x));
    return u;
}
__device__ __forceinline__ void mma_tf32(float* c, uint32_t a0, uint32_t a1,
                                         uint32_t a2, uint32_t a3,
                                         uint32_t b0, uint32_t b1) {
    asm volatile(
        "mma.sync.aligned.m16n8k8.row.col.f32.tf32.tf32.f32 "
        "{%0,%1,%2,%3}, {%4,%5,%6,%7}, {%8,%9}, {%0,%1,%2,%3};"
        : "+f"(c[0]), "+f"(c[1]), "+f"(c[2]), "+f"(c[3])
        : "r"(a0), "r"(a1), "r"(a2), "r"(a3), "r"(b0), "r"(b1));
}

#define SPAD 136

__global__ __launch_bounds__(256, 2)
void tgemm_b(GB g, int lda, int ldc, int ldadd, int M, int N, int K)
{
    const int z = blockIdx.z;
    const float* __restrict__ A    = g.A[z];
    const float* __restrict__ B    = g.B[z];
    float*       __restrict__ C    = g.C[z];
    float*                    C2   = g.C2[z];
    const float*              bias = g.bias[z];
    const float*              addm = g.addm[z];

    __shared__ uint32_t As[2][16][SPAD];
    __shared__ uint32_t Bs[2][16][SPAD];

    const int tid  = threadIdx.x;
    const int bm   = blockIdx.y * 128;
    const int bn   = blockIdx.x * 128;
    const int lane = tid & 31;
    const int gid  = lane >> 2;
    const int tg   = lane & 3;
    const int warp = tid >> 5;
    const int wm   = warp & 3;
    const int wn   = warp >> 2;

    float acc[2][8][4];
#pragma unroll
    for (int mt = 0; mt < 2; mt++)
#pragma unroll
        for (int nt = 0; nt < 8; nt++)
#pragma unroll
            for (int c = 0; c < 4; c++) acc[mt][nt][c] = 0.f;

    const int am  = tid >> 1;
    const int ak0 = (tid & 1) * 4;
    const int brr = tid >> 5;
    const int bcc = (tid & 31) * 4;

    const bool arow_ok = (bm + am < M);
    float4 av0, av1, bv0, bv1;

    auto ldtile = [&](int k0) {
        av0 = arow_ok ? *(const float4*)(A + (size_t)(bm + am) * lda + k0 + ak0)
                      : make_float4(0.f, 0.f, 0.f, 0.f);
        av1 = arow_ok ? *(const float4*)(A + (size_t)(bm + am) * lda + k0 + 8 + ak0)
                      : make_float4(0.f, 0.f, 0.f, 0.f);
        bv0 = *(const float4*)(B + (size_t)(k0 + brr) * N + bn + bcc);
        bv1 = *(const float4*)(B + (size_t)(k0 + 8 + brr) * N + bn + bcc);
    };
    auto sttile = [&](int p) {
        As[p][ak0 + 0][am] = f2tf32(av0.x);
        As[p][ak0 + 1][am] = f2tf32(av0.y);
        As[p][ak0 + 2][am] = f2tf32(av0.z);
        As[p][ak0 + 3][am] = f2tf32(av0.w);
        As[p][8 + ak0 + 0][am] = f2tf32(av1.x);
        As[p][8 + ak0 + 1][am] = f2tf32(av1.y);
        As[p][8 + ak0 + 2][am] = f2tf32(av1.z);
        As[p][8 + ak0 + 3][am] = f2tf32(av1.w);
        uint4 t0 = make_uint4(f2tf32(bv0.x), f2tf32(bv0.y), f2tf32(bv0.z), f2tf32(bv0.w));
        uint4 t1 = make_uint4(f2tf32(bv1.x), f2tf32(bv1.y), f2tf32(bv1.z), f2tf32(bv1.w));
        *(uint4*)(&Bs[p][brr][bcc]) = t0;
        *(uint4*)(&Bs[p][8 + brr][bcc]) = t1;
    };

    ldtile(0);
    sttile(0);

    const int nt_tiles = K / 16;
    for (int kt = 0; kt < nt_tiles; kt++) {
        const int p = kt & 1;
        const bool more = (kt + 1 < nt_tiles);
        if (more) ldtile((kt + 1) * 16);
        __syncthreads();

#pragma unroll
        for (int ks = 0; ks < 2; ks++) {
            const int kk = ks * 8;
            uint32_t bf[8][2];
#pragma unroll
            for (int nt = 0; nt < 8; nt++) {
                const int n0 = wn * 64 + nt * 8 + gid;
                bf[nt][0] = Bs[p][kk + tg][n0];
                bf[nt][1] = Bs[p][kk + tg + 4][n0];
            }
#pragma unroll
            for (int mt = 0; mt < 2; mt++) {
                const int m0 = wm * 32 + mt * 16;
                uint32_t a0 = As[p][kk + tg][m0 + gid];
                uint32_t a1 = As[p][kk + tg][m0 + gid + 8];
                uint32_t a2 = As[p][kk + tg + 4][m0 + gid];
                uint32_t a3 = As[p][kk + tg + 4][m0 + gid + 8];
#pragma unroll
                for (int nt = 0; nt < 8; nt++)
                    mma_tf32(acc[mt][nt], a0, a1, a2, a3, bf[nt][0], bf[nt][1]);
            }
        }
        if (more) sttile(p ^ 1);
    }

#pragma unroll
    for (int mt = 0; mt < 2; mt++) {
        const int r0 = bm + wm * 32 + mt * 16 + gid;
        const int r1 = r0 + 8;
#pragma unroll
        for (int nt = 0; nt < 8; nt++) {
            const int n = bn + wn * 64 + nt * 8 + tg * 2;
            float2 v0 = make_float2(acc[mt][nt][0], acc[mt][nt][1]);
            float2 v1 = make_float2(acc[mt][nt][2], acc[mt][nt][3]);
            if (bias) {
                float b0 = bias[n], b1 = bias[n + 1];
                v0.x += b0; v0.y += b1;
                v1.x += b0; v1.y += b1;
            }
            if (r0 < M) {
                float2 o = v0;
                if (addm) {
                    const float2 ad = *(const float2*)(addm + (size_t)r0 * ldadd + n);
                    o.x += ad.x; o.y += ad.y;
                }
                *(float2*)(C + (size_t)r0 * ldc + n) = o;
                if (C2) *(float2*)(C2 + (size_t)r0 * ldc + n) = o;
            }
            if (r1 < M) {
                float2 o = v1;
                if (addm) {
                    const float2 ad = *(const float2*)(addm + (size_t)r1 * ldadd + n);
                    o.x += ad.x; o.y += ad.y;
                }
                *(float2*)(C + (size_t)r1 * ldc + n) = o;
                if (C2) *(float2*)(C2 + (size_t)r1 * ldc + n) = o;
            }
        }
    }
}

// ---------------- small batched kernels ---------------------------------------
__global__ void zero_int(int* p, int n) {
    int i = blockIdx.x * blockDim.x + threadIdx.x;
    if (i < n) p[i] = 0;
}
__global__ void build_adj_b(ADJB g) {
    int z = blockIdx.y;
    int i = blockIdx.x * blockDim.x + threadIdx.x;
    if (i >= g.ecnt[z]) return;
    int d = g.dst[z][i];
    if (d < EXER_N) return;
    int dl = d - EXER_N;
    int slot = atomicAdd(&g.cnt[z][dl], 1);
    if (slot < CAP) g.adj[z][(size_t)dl * CAP + slot] = g.src[z][i];
}
__global__ void bz_kernel(const float* __restrict__ gb, const float* __restrict__ fcW,
                          const float* __restrict__ fcb, float* __restrict__ bz) {
    int p = blockIdx.x, n = threadIdx.x;
    const float* g = gb + (size_t)p * HD;
    const float* W = fcW + (size_t)p * HD * DD;
    float s = fcb[(size_t)p * DD + n];
    for (int k = 0; k < HD; k++) s += g[k] * W[(size_t)k * DD + n];
    bz[(size_t)p * DD + n] = s;
}
__global__ void el_er_b(EEB g) {
    int z = blockIdx.y;
    int n = blockIdx.x, t = threadIdx.x;
    const float* fr = g.f[z] + (size_t)n * HD;
    const float* al = g.al[z];
    const float* ar = g.ar[z];
    float pel[3], per[3];
#pragma unroll
    for (int h = 0; h < 3; h++) {
        float v = fr[h * DD + t];
        pel[h] = v * al[h * DD + t];
        per[h] = v * ar[h * DD + t];
    }
#pragma unroll
    for (int off = 16; off; off >>= 1) {
#pragma unroll
        for (int h = 0; h < 3; h++) {
            pel[h] += __shfl_xor_sync(0xffffffffu, pel[h], off);
            per[h] += __shfl_xor_sync(0xffffffffu, per[h], off);
        }
    }
    __shared__ float red[4][6];
    int w = t >> 5;
    if ((t & 31) == 0) {
#pragma unroll
        for (int h = 0; h < 3; h++) { red[w][h] = pel[h]; red[w][3 + h] = per[h]; }
    }
    __syncthreads();
    if (t < 6) {
        float v = red[0][t] + red[1][t] + red[2][t] + red[3][t];
        if (t < 3) g.el[z][(size_t)n * 3 + t] = v;
        else       g.er[z][(size_t)n * 3 + (t - 3)] = v;
    }
}
__global__ void zlzr_b(ZZB g) {
    int z = blockIdx.y;
    int n = blockIdx.x, t = threadIdx.x;
    float v = g.z[z][(size_t)n * DD + t];
    float a = v * g.aW[z][t];
    float b = v * g.aW[z][DD + t];
#pragma unroll
    for (int off = 16; off; off >>= 1) {
        a += __shfl_xor_sync(0xffffffffu, a, off);
        b += __shfl_xor_sync(0xffffffffu, b, off);
    }
    __shared__ float red[4][2];
    int w = t >> 5;
    if ((t & 31) == 0) { red[w][0] = a; red[w][1] = b; }
    __syncthreads();
    if (t < 2) {
        float v2 = red[0][t] + red[1][t] + red[2][t] + red[3][t];
        if (t == 0) g.zl[z][n] = v2; else g.zr[z][n] = v2;
    }
}

// phase-B attn1 (single branch, float4 gather)
__global__ void attn1_b(A1B g) {
    int z = blockIdx.y;
    int dl = blockIdx.x, t = threadIdx.x;
    int deg = g.cnt[z][dl]; if (deg > CAP) deg = CAP;
    const float* elE = g.elE[z];
    const float* elS = g.elS[z];
    const float* fE  = g.fE[z];
    const float* fS  = g.fS[z];
    __shared__ int   ssrc[CAP];
    __shared__ float se[CAP * 3];
    __shared__ float sm[3], ssum[3];
    float er0 = g.erS[z][(size_t)dl * 3 + 0];
    float er1 = g.erS[z][(size_t)dl * 3 + 1];
    float er2 = g.erS[z][(size_t)dl * 3 + 2];
    if (t < deg) {
        int s = g.adj[z][(size_t)dl * CAP + t];
        ssrc[t] = s;
        const float* el = (s < EXER_N) ? (elE + (size_t)s * 3) : (elS + (size_t)(s - EXER_N) * 3);
        float e0 = el[0] + er0, e1 = el[1] + er1, e2 = el[2] + er2;
        se[t * 3 + 0] = e0 > 0.f ? e0 : 0.2f * e0;
        se[t * 3 + 1] = e1 > 0.f ? e1 : 0.2f * e1;
        se[t * 3 + 2] = e2 > 0.f ? e2 : 0.2f * e2;
    }
    __syncthreads();
    int w = t >> 5, lane = t & 31;
    if (w < 3) {
        float m = -3.0e38f;
        for (int j = lane; j < deg; j += 32) m = fmaxf(m, se[j * 3 + w]);
#pragma unroll
        for (int off = 16; off; off >>= 1) m = fmaxf(m, __shfl_xor_sync(0xffffffffu, m, off));
        float s = 0.f;
        for (int j = lane; j < deg; j += 32) s += expf(se[j * 3 + w] - m);
#pragma unroll
        for (int off = 16; off; off >>= 1) s += __shfl_xor_sync(0xffffffffu, s, off);
        if (lane == 0) { sm[w] = m; ssum[w] = s; }
    }
    __syncthreads();
    if (t < deg) {
#pragma unroll
        for (int h = 0; h < 3; h++)
            se[t * 3 + h] = expf(se[t * 3 + h] - sm[h]) / ssum[h];
    }
    __syncthreads();
    if (t < 96) {
        const int head = t >> 5;
        float4 a = make_float4(0.f, 0.f, 0.f, 0.f);
        for (int j = 0; j < deg; j++) {
            int s = ssrc[j];
            float wgt = se[j * 3 + head];
            const float* fr = (s < EXER_N) ? (fE + (size_t)s * HD)
                                           : (fS + (size_t)(s - EXER_N) * HD);
            float4 f = *(const float4*)(fr + 4 * t);
            a.x += wgt * f.x; a.y += wgt * f.y; a.z += wgt * f.z; a.w += wgt * f.w;
        }
        *(float4*)(g.rst[z] + (size_t)dl * HD + 4 * t) = a;
    }
}

// phase-D merged attn1: two branches share the exer-side gather
__global__ void attn1_m(A1M g) {
    int z = blockIdx.y;                       // slot
    int dl = blockIdx.x, t = threadIdx.x;
    int deg = g.cnt[z][dl]; if (deg > CAP) deg = CAP;
    const float* elE = g.elE[z];
    const float* fE  = g.fE[z];
    __shared__ int   ssrc[CAP];
    __shared__ float seX[CAP * 3], seP[CAP * 3];
    __shared__ float smX[3], ssumX[3], smP[3], ssumP[3];
    float erX[3], erP[3];
#pragma unroll
    for (int h = 0; h < 3; h++) {
        erX[h] = g.erSX[z][(size_t)dl * 3 + h];
        erP[h] = g.erSP[z][(size_t)dl * 3 + h];
    }
    if (t < deg) {
        int s = g.adj[z][(size_t)dl * CAP + t];
        ssrc[t] = s;
        const float* elx;
        const float* elp;
        if (s < EXER_N) { elx = elE + (size_t)s * 3; elp = elx; }
        else {
            elx = g.elSX[z] + (size_t)(s - EXER_N) * 3;
            elp = g.elSP[z] + (size_t)(s - EXER_N) * 3;
        }
#pragma unroll
        for (int h = 0; h < 3; h++) {
            float ex = elx[h] + erX[h];
            float ep = elp[h] + erP[h];
            seX[t * 3 + h] = ex > 0.f ? ex : 0.2f * ex;
            seP[t * 3 + h] = ep > 0.f ? ep : 0.2f * ep;
        }
    }
    __syncthreads();
    int w = t >> 5, lane = t & 31;
    if (w < 3) {
        float mX = -3.0e38f, mP = -3.0e38f;
        for (int j = lane; j < deg; j += 32) {
            mX = fmaxf(mX, seX[j * 3 + w]);
            mP = fmaxf(mP, seP[j * 3 + w]);
        }
#pragma unroll
        for (int off = 16; off; off >>= 1) {
            mX = fmaxf(mX, __shfl_xor_sync(0xffffffffu, mX, off));
            mP = fmaxf(mP, __shfl_xor_sync(0xffffffffu, mP, off));
        }
        float sX = 0.f, sP = 0.f;
        for (int j = lane; j < deg; j += 32) {
            sX += expf(seX[j * 3 + w] - mX);
            sP += expf(seP[j * 3 + w] - mP);
        }
#pragma unroll
        for (int off = 16; off; off >>= 1) {
            sX += __shfl_xor_sync(0xffffffffu, sX, off);
            sP += __shfl_xor_sync(0xffffffffu, sP, off);
        }
        if (lane == 0) { smX[w] = mX; ssumX[w] = sX; smP[w] = mP; ssumP[w] = sP; }
    }
    __syncthreads();
    if (t < deg) {
#pragma unroll
        for (int h = 0; h < 3; h++) {
            seX[t * 3 + h] = expf(seX[t * 3 + h] - smX[h]) / ssumX[h];
            seP[t * 3 + h] = expf(seP[t * 3 + h] - smP[h]) / ssumP[h];
        }
    }
    __syncthreads();
    if (t < 96) {
        const int head = t >> 5;
        float4 aX = make_float4(0.f, 0.f, 0.f, 0.f);
        float4 aP = make_float4(0.f, 0.f, 0.f, 0.f);
        for (int j = 0; j < deg; j++) {
            int s = ssrc[j];
            float wX = seX[j * 3 + head];
            float wP = seP[j * 3 + head];
            if (s < EXER_N) {
                float4 f = *(const float4*)(fE + (size_t)s * HD + 4 * t);
                aX.x += wX * f.x; aX.y += wX * f.y; aX.z += wX * f.z; aX.w += wX * f.w;
                aP.x += wP * f.x; aP.y += wP * f.y; aP.z += wP * f.z; aP.w += wP * f.w;
            } else {
                float4 fx = *(const float4*)(g.fSX[z] + (size_t)(s - EXER_N) * HD + 4 * t);
                float4 fp = *(const float4*)(g.fSP[z] + (size_t)(s - EXER_N) * HD + 4 * t);
                aX.x += wX * fx.x; aX.y += wX * fx.y; aX.z += wX * fx.z; aX.w += wX * fx.w;
                aP.x += wP * fp.x; aP.y += wP * fp.y; aP.z += wP * fp.z; aP.w += wP * fp.w;
            }
        }
        *(float4*)(g.rstX[z] + (size_t)dl * HD + 4 * t) = aX;
        *(float4*)(g.rstP[z] + (size_t)dl * HD + 4 * t) = aP;
    }
}

// phase-B attn2 (single branch)
__global__ void attn2_b(A2B g, int ldo) {
    int z = blockIdx.y;
    int dl = blockIdx.x, t = threadIdx.x;
    int deg = g.cnt[z][dl]; if (deg > CAP) deg = CAP;
    const float* zlE = g.zlE[z];
    const float* zlS = g.zlS[z];
    const float* zE  = g.zE[z];
    const float* zS  = g.zS[z];
    __shared__ int   ssrc[CAP];
    __shared__ float se[CAP];
    __shared__ float smx, ssm;
    float zr = g.zrS[z][dl];
    if (t < deg) {
        int s = g.adj[z][(size_t)dl * CAP + t];
        ssrc[t] = s;
        float zl = (s < EXER_N) ? zlE[s] : zlS[s - EXER_N];
        se[t] = zl + zr;
    }
    __syncthreads();
    if (t < 32) {
        float m = -3.0e38f;
        for (int j = t; j < deg; j += 32) m = fmaxf(m, se[j]);
#pragma unroll
        for (int off = 16; off; off >>= 1) m = fmaxf(m, __shfl_xor_sync(0xffffffffu, m, off));
        float s = 0.f;
        for (int j = t; j < deg; j += 32) s += expf(se[j] - m);
#pragma unroll
        for (int off = 16; off; off >>= 1) s += __shfl_xor_sync(0xffffffffu, s, off);
        if (t == 0) { smx = m; ssm = s; }
    }
    __syncthreads();
    if (t < deg) se[t] = expf(se[t] - smx) / ssm;
    __syncthreads();
    float acc = 0.f;
    for (int j = 0; j < deg; j++) {
        int s = ssrc[j];
        const float* zrow = (s < EXER_N) ? (zE + (size_t)s * DD) : (zS + (size_t)(s - EXER_N) * DD);
        acc += se[j] * zrow[t];
    }
    g.out[z][(size_t)dl * ldo + t] = acc;
    if (g.out2[z]) g.out2[z][(size_t)dl * ldo + t] = acc;
}

// phase-D merged attn2
__global__ void attn2_m(A2M g, int ldo) {
    int z = blockIdx.y;                       // slot
    int dl = blockIdx.x, t = threadIdx.x;
    int deg = g.cnt[z][dl]; if (deg > CAP) deg = CAP;
    const float* zlE = g.zlE[z];
    const float* zE  = g.zE[z];
    __shared__ int   ssrc[CAP];
    __shared__ float seX[CAP], seP[CAP];
    __shared__ float smxX, ssmX, smxP, ssmP;
    float zrX = g.zrSX[z][dl];
    float zrP = g.zrSP[z][dl];
    if (t < deg) {
        int s = g.adj[z][(size_t)dl * CAP + t];
        ssrc[t] = s;
        float zlx, zlp;
        if (s < EXER_N) { zlx = zlE[s]; zlp = zlx; }
        else {
            zlx = g.zlSX[z][s - EXER_N];
            zlp = g.zlSP[z][s - EXER_N];
        }
        seX[t] = zlx + zrX;
        seP[t] = zlp + zrP;
    }
    __syncthreads();
    int w = t >> 5, lane = t & 31;
    if (w < 2) {
        float* se = (w == 0) ? seX : seP;
        float m = -3.0e38f;
        for (int j = lane; j < deg; j += 32) m = fmaxf(m, se[j]);
#pragma unroll
        for (int off = 16; off; off >>= 1) m = fmaxf(m, __shfl_xor_sync(0xffffffffu, m, off));
        float s = 0.f;
        for (int j = lane; j < deg; j += 32) s += expf(se[j] - m);
#pragma unroll
        for (int off = 16; off; off >>= 1) s += __shfl_xor_sync(0xffffffffu, s, off);
        if (lane == 0) {
            if (w == 0) { smxX = m; ssmX = s; }
            else        { smxP = m; ssmP = s; }
        }
    }
    __syncthreads();
    if (t < deg) {
        seX[t] = expf(seX[t] - smxX) / ssmX;
        seP[t] = expf(seP[t] - smxP) / ssmP;
    }
    __syncthreads();
    float accX = 0.f, accP = 0.f;
    for (int j = 0; j < deg; j++) {
        int s = ssrc[j];
        if (s < EXER_N) {
            float v = zE[(size_t)s * DD + t];
            accX += seX[j] * v;
            accP += seP[j] * v;
        } else {
            accX += seX[j] * g.zSX[z][(size_t)(s - EXER_N) * DD + t];
            accP += seP[j] * g.zSP[z][(size_t)(s - EXER_N) * DD + t];
        }
    }
    g.outX[z][(size_t)dl * ldo + t] = accX;
    g.outP[z][(size_t)dl * ldo + t] = accP;
}

// SSL ------------------------------------------------------------------------
__global__ void norm_rows_b(NRB g, const int* __restrict__ ids) {
    int z = blockIdx.y;
    int i = blockIdx.x, t = threadIdx.x;
    int r = ids[i];
    float v = g.emb[z][(size_t)r * DD + t];
    float sq = v * v;
#pragma unroll
    for (int off = 16; off; off >>= 1) sq += __shfl_xor_sync(0xffffffffu, sq, off);
    __shared__ float w4[4];
    if ((t & 31) == 0) w4[t >> 5] = sq;
    __syncthreads();
    float tot = w4[0] + w4[1] + w4[2] + w4[3];
    float nrm = sqrtf(tot);
    g.out[z][(size_t)i * DD + t] = v / fmaxf(nrm, 1e-12f);
}
__global__ void colsum(const float* __restrict__ nbp, float* __restrict__ S) {
    int t = threadIdx.x;
    float s = 0.f;
    for (int i = 0; i < BATCH; i++) s += nbp[(size_t)i * DD + t];
    S[t] = s;
}
__global__ void loss_kernel(const float* __restrict__ nb, const float* __restrict__ nbp,
                            const float* __restrict__ S, float* __restrict__ out) {
    int t = threadIdx.x;
    float lsum = 0.f;
    for (int i = t; i < BATCH; i += 256) {
        const float* x = nb  + (size_t)i * DD;
        const float* y = nbp + (size_t)i * DD;
        float dg = 0.f, rs = 0.f;
        for (int d = 0; d < DD; d++) {
            float xv = x[d];
            dg += xv * y[d];
            rs += xv * S[d];
        }
        float divided = expf(dg * 5.0f) / (rs * 5.0f + 1e-8f);
        lsum += -logf(fmaxf(divided, 1e-8f));
    }
    __shared__ float red[256];
    red[t] = lsum;
    __syncthreads();
    for (int s = 128; s; s >>= 1) { if (t < s) red[t] += red[t + s]; __syncthreads(); }
    if (t == 0) out[0] = red[0];
}

// ---------------- host orchestration ------------------------------------------
extern "C" void kernel_launch(void* const* d_in, const int* in_sizes, int n_in,
                              void* d_out_, int out_size)
{
    const float* stu_table  = (const float*)d_in[0];
    const float* exer_table = (const float*)d_in[1];
    const float* gat_W  = (const float*)d_in[2];
    const float* attn_l = (const float*)d_in[3];
    const float* attn_r = (const float*)d_in[4];
    const float* gat_b  = (const float*)d_in[5];
    const float* fc_W   = (const float*)d_in[6];
    const float* fc_b   = (const float*)d_in[7];
    const float* aW     = (const float*)d_in[8];
    const float* f1W    = (const float*)d_in[9];
    const float* f1b    = (const float*)d_in[10];
    const float* f2W    = (const float*)d_in[11];
    const float* f2b    = (const float*)d_in[12];
    const int* e_src[3] = {(const int*)d_in[13], (const int*)d_in[15], (const int*)d_in[21]};
    const int* e_dst[3] = {(const int*)d_in[14], (const int*)d_in[16], (const int*)d_in[22]};
    int e_n[3] = {in_sizes[13], in_sizes[15], in_sizes[21]};
    const int* stu_id = (const int*)d_in[23];
    float* d_out = (float*)d_out_;
    (void)n_in;

    float* FA = nullptr; int* IA = nullptr;
    cudaGetSymbolAddress((void**)&FA, g_farena);
    cudaGetSymbolAddress((void**)&IA, g_iarena);

    float* fE    = FA + O_fE;
    float* elE   = FA + O_elE;
    float* erD   = FA + O_erD;
    float* zE    = FA + O_zE;
    float* zlE   = FA + O_zlE;
    float* zrD   = FA + O_zrD;
    float* bz    = FA + O_bz;
    float* ABCD  = FA + O_ABCD;
    float* ABPCD = FA + O_ABPCD;
    float* stu1  = FA + O_stu1;
    float* stu1p = FA + O_stu1p;
    float* XYX   = FA + O_XYX;
    float* XYP   = FA + O_XYP;
    float* stu2  = FA + O_stu2;
    float* stu2p = FA + O_stu2p;
    float* nb    = FA + O_nb;
    float* nbp   = FA + O_nbp;
    float* Sv    = FA + O_S;
    float* lossD = FA + O_lossd;

    const int pidx[3] = {0, 1, 4};
    const int gM_E = (EXER_N + 127) / 128;
    const int gM_S = (STU_N + 127) / 128;

    auto scr  = [&](int sc, size_t off) { return FA + O_SCR + (size_t)sc * SC_TOT + off; };
    auto adjP = [&](int s) { return IA + OI_adj + (size_t)s * STU_N * CAP; };
    auto cntP = [&](int s) { return IA + OI_cnt + (size_t)s * STU_N; };

    // ---- bias precompute + adjacency ----
    bz_kernel<<<5, 128>>>(gat_b, fc_W, fc_b, bz);
    zero_int<<<(3 * STU_N + 255) / 256, 256>>>(IA + OI_cnt, 3 * STU_N);
    {
        ADJB g{};
        int max_e = 0;
        for (int s = 0; s < 3; s++) {
            g.src[s] = e_src[s]; g.dst[s] = e_dst[s]; g.ecnt[s] = e_n[s];
            g.adj[s] = adjP(s);  g.cnt[s] = cntP(s);
            if (e_n[s] > max_e) max_e = e_n[s];
        }
        build_adj_b<<<dim3((max_e + 255) / 256, 3), 256>>>(g);
    }

    // ---- phase A: exer-side invariants (batched z=3) ----
    {
        GB g{};
        for (int s = 0; s < 3; s++) {
            g.A[s] = exer_table;
            g.B[s] = gat_W + (size_t)pidx[s] * DD * HD;
            g.C[s] = fE + (size_t)s * EXER_N * HD;
        }
        tgemm_b<<<dim3(HD / 128, gM_E, 3), 256>>>(g, DD, HD, 0, EXER_N, HD, DD);
    }
    {
        EEB g{};
        for (int s = 0; s < 3; s++) {
            g.f[s]  = fE + (size_t)s * EXER_N * HD;
            g.al[s] = attn_l + (size_t)pidx[s] * HD;
            g.ar[s] = attn_r + (size_t)pidx[s] * HD;
            g.el[s] = elE + (size_t)s * EXER_N * 3;
            g.er[s] = erD;
        }
        el_er_b<<<dim3(EXER_N, 3), 128>>>(g);
    }
    {
        GB g{};
        for (int s = 0; s < 3; s++) {
            g.A[s] = fE + (size_t)s * EXER_N * HD;
            g.B[s] = fc_W + (size_t)pidx[s] * HD * DD;
            g.C[s] = zE + (size_t)s * EXER_N * DD;
            g.bias[s] = bz + (size_t)pidx[s] * DD;
        }
        tgemm_b<<<dim3(DD / 128, gM_E, 3), 256>>>(g, HD, DD, 0, EXER_N, DD, HD);
    }
    {
        ZZB g{};
        for (int s = 0; s < 3; s++) {
            g.z[s]  = zE + (size_t)s * EXER_N * DD;
            g.aW[s] = aW + (size_t)pidx[s] * 2 * DD;
            g.zl[s] = zlE + (size_t)s * EXER_N;
            g.zr[s] = zrD;
        }
        zlzr_b<<<dim3(EXER_N, 3), 128>>>(g);
    }

    // ---- layers 2,3 (self-loop only), batched z=2 ----
    {
        GB g{};
        for (int i = 0; i < 2; i++) {
            g.A[i] = stu_table;
            g.B[i] = gat_W + (size_t)(2 + i) * DD * HD;
            g.C[i] = scr(i, SC_fS);
        }
        tgemm_b<<<dim3(HD / 128, gM_S, 2), 256>>>(g, DD, HD, 0, STU_N, HD, DD);
    }
    {
        GB g{};
        for (int i = 0; i < 2; i++) {
            int coff = (i == 0) ? 2 * DD : 3 * DD;
            g.A[i] = scr(i, SC_fS);
            g.B[i] = fc_W + (size_t)(2 + i) * HD * DD;
            g.C[i] = ABCD + coff;
            g.C2[i] = ABPCD + coff;
            g.bias[i] = bz + (size_t)(2 + i) * DD;
        }
        tgemm_b<<<dim3(DD / 128, gM_S, 2), 256>>>(g, HD, 4 * DD, 0, STU_N, DD, HD);
    }

    // ---- phase B: round-1 GAT (a, b, bp), batched z=3 ----
    {
        const int slot[3] = {0, 1, 2};
        {
            GB g{};
            for (int i = 0; i < 3; i++) {
                g.A[i] = stu_table;
                g.B[i] = gat_W + (size_t)pidx[slot[i]] * DD * HD;
                g.C[i] = scr(i, SC_fS);
            }
            tgemm_b<<<dim3(HD / 128, gM_S, 3), 256>>>(g, DD, HD, 0, STU_N, HD, DD);
        }
        {
            EEB g{};
            for (int i = 0; i < 3; i++) {
                g.f[i]  = scr(i, SC_fS);
                g.al[i] = attn_l + (size_t)pidx[slot[i]] * HD;
                g.ar[i] = attn_r + (size_t)pidx[slot[i]] * HD;
                g.el[i] = scr(i, SC_elS);
                g.er[i] = scr(i, SC_erS);
            }
            el_er_b<<<dim3(STU_N, 3), 128>>>(g);
        }
        {
            A1B g{};
            for (int i = 0; i < 3; i++) {
                int s = slot[i];
                g.adj[i] = adjP(s); g.cnt[i] = cntP(s);
                g.elE[i] = elE + (size_t)s * EXER_N * 3;
                g.elS[i] = scr(i, SC_elS);
                g.erS[i] = scr(i, SC_erS);
                g.fE[i]  = fE + (size_t)s * EXER_N * HD;
                g.fS[i]  = scr(i, SC_fS);
                g.rst[i] = scr(i, SC_rst);
            }
            attn1_b<<<dim3(STU_N, 3), 128>>>(g);
        }
        {
            GB g{};
            for (int i = 0; i < 3; i++) {
                g.A[i] = scr(i, SC_rst);
                g.B[i] = fc_W + (size_t)pidx[slot[i]] * HD * DD;
                g.C[i] = scr(i, SC_zS);
                g.bias[i] = bz + (size_t)pidx[slot[i]] * DD;
            }
            tgemm_b<<<dim3(DD / 128, gM_S, 3), 256>>>(g, HD, DD, 0, STU_N, DD, HD);
        }
        {
            ZZB g{};
            for (int i = 0; i < 3; i++) {
                g.z[i]  = scr(i, SC_zS);
                g.aW[i] = aW + (size_t)pidx[slot[i]] * 2 * DD;
                g.zl[i] = scr(i, SC_zlS);
                g.zr[i] = scr(i, SC_zrS);
            }
            zlzr_b<<<dim3(STU_N, 3), 128>>>(g);
        }
        {
            A2B g{};
            float* outb[3]  = {ABCD, ABCD + DD, ABPCD + DD};
            float* outb2[3] = {ABPCD, nullptr, nullptr};
            for (int i = 0; i < 3; i++) {
                int s = slot[i];
                g.adj[i] = adjP(s); g.cnt[i] = cntP(s);
                g.zlE[i] = zlE + (size_t)s * EXER_N;
                g.zlS[i] = scr(i, SC_zlS);
                g.zrS[i] = scr(i, SC_zrS);
                g.zE[i]  = zE + (size_t)s * EXER_N * DD;
                g.zS[i]  = scr(i, SC_zS);
                g.out[i]  = outb[i];
                g.out2[i] = outb2[i];
            }
            attn2_b<<<dim3(STU_N, 3), 128>>>(g, 4 * DD);
        }
    }

    // ---- fuse1: K=512 GEMM + residual, batched z=2 ----
    {
        GB g{};
        g.A[0] = ABCD;  g.C[0] = stu1;  g.bias[0] = f1b; g.addm[0] = stu_table;
        g.A[1] = ABPCD; g.C[1] = stu1p; g.bias[1] = f1b; g.addm[1] = stu_table;
        g.B[0] = f1W; g.B[1] = f1W;
        tgemm_b<<<dim3(DD / 128, gM_S, 2), 256>>>(g, 4 * DD, DD, DD, STU_N, DD, 4 * DD);
    }

    // ---- phase D: expr2 on both branches ----
    // instances: 0 = (stu1, slot0), 1 = (stu1, slot1), 2 = (stu1p, slot0), 3 = (stu1p, slot1)
    {
        const float* xS[4] = {stu1, stu1, stu1p, stu1p};
        const int slot4[4] = {0, 1, 0, 1};
        {
            GB g{};
            for (int i = 0; i < 4; i++) {
                g.A[i] = xS[i];
                g.B[i] = gat_W + (size_t)pidx[slot4[i]] * DD * HD;
                g.C[i] = scr(i, SC_fS);
            }
            tgemm_b<<<dim3(HD / 128, gM_S, 4), 256>>>(g, DD, HD, 0, STU_N, HD, DD);
        }
        {
            EEB g{};
            for (int i = 0; i < 4; i++) {
                g.f[i]  = scr(i, SC_fS);
                g.al[i] = attn_l + (size_t)pidx[slot4[i]] * HD;
                g.ar[i] = attn_r + (size_t)pidx[slot4[i]] * HD;
                g.el[i] = scr(i, SC_elS);
                g.er[i] = scr(i, SC_erS);
            }
            el_er_b<<<dim3(STU_N, 4), 128>>>(g);
        }
        {
            A1M g{};
            for (int s = 0; s < 2; s++) {           // slot s; X=scr(s), P=scr(s+2)
                g.adj[s] = adjP(s); g.cnt[s] = cntP(s);
                g.elE[s] = elE + (size_t)s * EXER_N * 3;
                g.fE[s]  = fE + (size_t)s * EXER_N * HD;
                g.elSX[s] = scr(s, SC_elS);     g.elSP[s] = scr(s + 2, SC_elS);
                g.erSX[s] = scr(s, SC_erS);     g.erSP[s] = scr(s + 2, SC_erS);
                g.fSX[s]  = scr(s, SC_fS);      g.fSP[s]  = scr(s + 2, SC_fS);
                g.rstX[s] = scr(s, SC_rst);     g.rstP[s] = scr(s + 2, SC_rst);
            }
            attn1_m<<<dim3(STU_N, 2), 128>>>(g);
        }
        {
            GB g{};
            for (int i = 0; i < 4; i++) {
                g.A[i] = scr(i, SC_rst);
                g.B[i] = fc_W + (size_t)pidx[slot4[i]] * HD * DD;
                g.C[i] = scr(i, SC_zS);
                g.bias[i] = bz + (size_t)pidx[slot4[i]] * DD;
            }
            tgemm_b<<<dim3(DD / 128, gM_S, 4), 256>>>(g, HD, DD, 0, STU_N, DD, HD);
        }
        {
            ZZB g{};
            for (int i = 0; i < 4; i++) {
                g.z[i]  = scr(i, SC_zS);
                g.aW[i] = aW + (size_t)pidx[slot4[i]] * 2 * DD;
                g.zl[i] = scr(i, SC_zlS);
                g.zr[i] = scr(i, SC_zrS);
            }
            zlzr_b<<<dim3(STU_N, 4), 128>>>(g);
        }
        {
            A2M g{};
            for (int s = 0; s < 2; s++) {
                g.adj[s] = adjP(s); g.cnt[s] = cntP(s);
                g.zlE[s] = zlE + (size_t)s * EXER_N;
                g.zE[s]  = zE + (size_t)s * EXER_N * DD;
                g.zlSX[s] = scr(s, SC_zlS);     g.zlSP[s] = scr(s + 2, SC_zlS);
                g.zrSX[s] = scr(s, SC_zrS);     g.zrSP[s] = scr(s + 2, SC_zrS);
                g.zSX[s]  = scr(s, SC_zS);      g.zSP[s]  = scr(s + 2, SC_zS);
                g.outX[s] = XYX + (size_t)s * DD;
                g.outP[s] = XYP + (size_t)s * DD;
            }
            attn2_m<<<dim3(STU_N, 2), 128>>>(g, 2 * DD);
        }
    }

    // ---- fusion2: K=256 + residual, batched z=2; stu2 dual-stored to d_out ----
    const int NOUT = STU_N * DD;
    {
        GB g{};
        g.A[0] = XYX; g.C[0] = stu2;  g.bias[0] = f2b; g.addm[0] = stu1;
        g.A[1] = XYP; g.C[1] = stu2p; g.bias[1] = f2b; g.addm[1] = stu1p;
        g.B[0] = f2W; g.B[1] = f2W;
        if (out_size >= NOUT) g.C2[0] = d_out;
        tgemm_b<<<dim3(DD / 128, gM_S, 2), 256>>>(g, 2 * DD, DD, DD, STU_N, DD, 2 * DD);
    }

    float* lossdst = lossD;
    if (out_size == 1) lossdst = d_out;
    else if (out_size > NOUT) lossdst = d_out + (out_size - 1);

    {
        NRB g{};
        g.emb[0] = stu2;  g.out[0] = nb;
        g.emb[1] = stu2p; g.out[1] = nbp;
        norm_rows_b<<<dim3(BATCH, 2), 128>>>(g, stu_id);
    }
    colsum<<<1, 128>>>(nbp, Sv);
    loss_kernel<<<1, 256>>>(nb, nbp, Sv, lossdst);
}